// round 3
// baseline (speedup 1.0000x reference)
#include <cuda_runtime.h>
#include <math.h>

#define HH 512
#define WW 512
#define NB 2
#define HWSZ (HH*WW)          // 262144
#define NHW (NB*HWSZ)         // 524288
#define PARTS 128

// ---------------- scratch (device globals; no allocation allowed) -------------
__device__ float g_feat [NB*32*HWSZ];
__device__ float g_aux  [NB*32*HWSZ];
__device__ float g_auxb1[NB*32*HWSZ];
__device__ float g_z    [NHW];
__device__ float g_inp  [NHW];
__device__ float g_xm9  [NB*9*HWSZ];
__device__ float g_xm25 [NB*25*HWSZ];
__device__ float g_img2 [NB*3*HWSZ];
__device__ float g_part [32*PARTS*2];
__device__ float g_scale1[32], g_shift1[32];
__device__ float g_scale2[1],  g_shift2[1];
__device__ unsigned g_hist[4][256];
__device__ unsigned g_prefix[4];
__device__ int      g_remain[4];
__device__ float    g_thr[4];

// ---------------- packed f32x2 helpers ----------------------------------------
__device__ __forceinline__ void ffma2(unsigned long long& d,
                                      unsigned long long a, unsigned long long b){
    asm("fma.rn.f32x2 %0, %1, %2, %0;" : "+l"(d) : "l"(a), "l"(b));
}
__device__ __forceinline__ unsigned long long pack2(float lo, float hi){
    unsigned long long u;
    asm("mov.b64 %0, {%1, %2};" : "=l"(u) : "f"(lo), "f"(hi));
    return u;
}
__device__ __forceinline__ float2 unpack2(unsigned long long u){
    float2 v;
    asm("mov.b64 {%0, %1}, %2;" : "=f"(v.x), "=f"(v.y) : "l"(u));
    return v;
}

// ---------------- 3x3 conv, f32x2 packed: 8 oc x (2px x 4rows) per thread ------
// block (32,8); output tile 64 wide x 32 tall; double-buffered input tile.
template<int IC, bool RELU>
__global__ __launch_bounds__(256) void conv3x3_f2(
    const float* __restrict__ in, const float* __restrict__ wt,
    float* __restrict__ out, int ocGroups)
{
    __shared__ float2 tile2[2][34][33];   // 66-float-wide halo rows
    __shared__ float2 wsm2[8*IC*9];       // weights duplicated (w,w)
    const int tid = threadIdx.y*32 + threadIdx.x;
    const int grp = blockIdx.z % ocGroups;
    const int n   = blockIdx.z / ocGroups;
    const int OC  = ocGroups*8;
    const int oc0 = grp*8;
    const int x0 = blockIdx.x*64, y0 = blockIdx.y*32;

    for (int i = tid; i < 8*IC*9; i += 256){
        float w = wt[oc0*IC*9 + i];
        wsm2[i] = make_float2(w, w);
    }

    // load channel 0 into buffer 0
    {
        float* tb = (float*)&tile2[0][0][0];
        const float* src = in + ((size_t)(n*IC))*HWSZ;
        for (int i = tid; i < 34*66; i += 256){
            int yy = i/66, xx = i - yy*66;
            int gy = y0+yy-1, gx = x0+xx-1;
            tb[yy*66+xx] = ((unsigned)gy<HH && (unsigned)gx<WW) ? src[(size_t)gy*WW+gx] : 0.f;
        }
    }
    __syncthreads();

    unsigned long long acc[8][4];
    #pragma unroll
    for (int o=0;o<8;o++)
        #pragma unroll
        for (int k=0;k<4;k++) acc[o][k]=0ull;

    for (int c = 0; c < IC; c++){
        const int cur = c & 1;
        // prefetch next channel into the other buffer
        if (c+1 < IC){
            float* tb = (float*)&tile2[cur^1][0][0];
            const float* src = in + ((size_t)(n*IC + c+1))*HWSZ;
            for (int i = tid; i < 34*66; i += 256){
                int yy = i/66, xx = i - yy*66;
                int gy = y0+yy-1, gx = x0+xx-1;
                tb[yy*66+xx] = ((unsigned)gy<HH && (unsigned)gx<WW) ? src[(size_t)gy*WW+gx] : 0.f;
            }
        }
        #pragma unroll
        for (int r=0;r<3;r++){
            unsigned long long wv[8][3];
            #pragma unroll
            for (int o=0;o<8;o++)
            #pragma unroll
            for (int s=0;s<3;s++)
                wv[o][s] = *(const unsigned long long*)&wsm2[(o*IC+c)*9 + r*3 + s];
            #pragma unroll
            for (int k=0;k<4;k++){
                const int row = threadIdx.y + 8*k + r;
                float2 A = tile2[cur][row][threadIdx.x];
                float2 B = tile2[cur][row][threadIdx.x+1];
                unsigned long long v0 = pack2(A.x, A.y);
                unsigned long long v1 = pack2(A.y, B.x);
                unsigned long long v2 = pack2(B.x, B.y);
                #pragma unroll
                for (int o=0;o<8;o++){
                    ffma2(acc[o][k], wv[o][0], v0);
                    ffma2(acc[o][k], wv[o][1], v1);
                    ffma2(acc[o][k], wv[o][2], v2);
                }
            }
        }
        __syncthreads();
    }

    #pragma unroll
    for (int o=0;o<8;o++)
    #pragma unroll
    for (int k=0;k<4;k++){
        float2 v = unpack2(acc[o][k]);
        if (RELU){ v.x = fmaxf(v.x,0.f); v.y = fmaxf(v.y,0.f); }
        size_t base = ((size_t)(n*OC + oc0 + o))*HWSZ
                    + (size_t)(y0+threadIdx.y+8*k)*WW + x0 + 2*threadIdx.x;
        *(float2*)&out[base] = v;
    }
}

// ---------------- x1 = conv(feat, w_out) ; inp = x1 + relu(bn(z)) --------------
__global__ __launch_bounds__(256) void wout_inp_k(
    const float* __restrict__ feat, const float* __restrict__ wt)
{
    __shared__ float tile[34][34];
    __shared__ float wsm[32*9];
    const int tid = threadIdx.y*32 + threadIdx.x;
    const int n = blockIdx.z;
    for (int i = tid; i < 288; i += 256) wsm[i] = wt[i];
    const int x0 = blockIdx.x*32, y0 = blockIdx.y*32;
    float acc[4] = {0.f,0.f,0.f,0.f};
    for (int c = 0; c < 32; c++) {
        __syncthreads();
        for (int i = tid; i < 34*34; i += 256) {
            int yy = i/34, xx = i%34;
            int gy = y0+yy-1, gx = x0+xx-1;
            float v = 0.f;
            if ((unsigned)gy < HH && (unsigned)gx < WW)
                v = feat[((size_t)(n*32 + c))*HWSZ + gy*WW + gx];
            tile[yy][xx] = v;
        }
        __syncthreads();
        #pragma unroll
        for (int r=0;r<3;r++)
        #pragma unroll
        for (int s=0;s<3;s++) {
            float w = wsm[c*9 + r*3 + s];
            #pragma unroll
            for (int k=0;k<4;k++)
                acc[k] = fmaf(w, tile[threadIdx.y + 8*k + r][threadIdx.x + s], acc[k]);
        }
    }
    float s2 = g_scale2[0], h2 = g_shift2[0];
    #pragma unroll
    for (int k=0;k<4;k++) {
        int idx = (y0+threadIdx.y+8*k)*WW + x0 + threadIdx.x;
        float zz = g_z[(size_t)n*HWSZ + idx];
        g_inp[(size_t)n*HWSZ + idx] = acc[k] + fmaxf(zz*s2 + h2, 0.f);
    }
}

// ---------------- batchnorm stats (deterministic two-stage) -------------------
__global__ __launch_bounds__(256) void stats1_k(const float* __restrict__ in, int C)
{
    const int c = blockIdx.y, p = blockIdx.x;
    const int chunk = NHW / PARTS;
    const int base = p*chunk;
    float s = 0.f, q = 0.f;
    for (int i = base + threadIdx.x; i < base + chunk; i += 256) {
        int nn = i / HWSZ, r = i - nn*HWSZ;
        float v = in[((size_t)(nn*C + c))*HWSZ + r];
        s += v; q += v*v;
    }
    __shared__ float ss[256], qq[256];
    ss[threadIdx.x]=s; qq[threadIdx.x]=q;
    __syncthreads();
    for (int o=128;o>0;o>>=1){
        if (threadIdx.x < o){ ss[threadIdx.x]+=ss[threadIdx.x+o]; qq[threadIdx.x]+=qq[threadIdx.x+o]; }
        __syncthreads();
    }
    if (threadIdx.x==0){
        g_part[(c*PARTS+p)*2+0]=ss[0];
        g_part[(c*PARTS+p)*2+1]=qq[0];
    }
}

__global__ void stats2_k(const float* __restrict__ g, const float* __restrict__ b,
                         float* __restrict__ scale, float* __restrict__ shift)
{
    const int c = blockIdx.x;
    __shared__ float ss[128], qq[128];
    ss[threadIdx.x] = g_part[(c*PARTS+threadIdx.x)*2+0];
    qq[threadIdx.x] = g_part[(c*PARTS+threadIdx.x)*2+1];
    __syncthreads();
    for (int o=64;o>0;o>>=1){
        if (threadIdx.x < o){ ss[threadIdx.x]+=ss[threadIdx.x+o]; qq[threadIdx.x]+=qq[threadIdx.x+o]; }
        __syncthreads();
    }
    if (threadIdx.x==0){
        float mean = ss[0]/(float)NHW;
        float var  = qq[0]/(float)NHW - mean*mean;
        float sc = g[c]*rsqrtf(var + 1e-5f);
        scale[c]=sc; shift[c]=b[c]-mean*sc;
    }
}

// ---------------- z = sum_c relu(bn(auxb1_c)) * b2w_c --------------------------
__global__ __launch_bounds__(256) void b2_k(const float* __restrict__ w2)
{
    __shared__ float s[32], h[32], ww[32];
    if (threadIdx.x < 32){ s[threadIdx.x]=g_scale1[threadIdx.x];
                           h[threadIdx.x]=g_shift1[threadIdx.x];
                           ww[threadIdx.x]=w2[threadIdx.x]; }
    __syncthreads();
    int i = blockIdx.x*256 + threadIdx.x;
    if (i >= NHW) return;
    int n = i / HWSZ, r = i - n*HWSZ;
    float acc = 0.f;
    #pragma unroll
    for (int c=0;c<32;c++){
        float v = g_auxb1[((size_t)(n*32+c))*HWSZ + r];
        acc += fmaxf(v*s[c]+h[c], 0.f)*ww[c];
    }
    g_z[i] = acc;
}

// ---------------- xm9 = aff3(inp) + conv(inp, d0) ------------------------------
__global__ __launch_bounds__(256) void xm9_k(const float* __restrict__ d0)
{
    __shared__ float tile[10][34];
    __shared__ float wsm[81];
    const int n = blockIdx.z;
    const int x0 = blockIdx.x*32, y0 = blockIdx.y*8;
    const int tid = threadIdx.y*32 + threadIdx.x;
    if (tid < 81) wsm[tid] = d0[tid];
    for (int i = tid; i < 340; i += 256){
        int yy=i/34, xx=i%34;
        int gy=y0+yy-1, gx=x0+xx-1;
        tile[yy][xx] = ((unsigned)gy<HH && (unsigned)gx<WW) ? g_inp[(size_t)n*HWSZ + gy*WW + gx] : 0.f;
    }
    __syncthreads();
    float nb[3][3];
    #pragma unroll
    for (int r=0;r<3;r++)
    #pragma unroll
    for (int s=0;s<3;s++) nb[r][s] = tile[threadIdx.y+r][threadIdx.x+s];
    float ctr = nb[1][1];
    int idx = (y0+threadIdx.y)*WW + x0 + threadIdx.x;
    #pragma unroll
    for (int t=0;t<9;t++){
        int ii=t/3, jj=t%3;
        float cv=0.f;
        #pragma unroll
        for (int r=0;r<3;r++)
        #pragma unroll
        for (int s=0;s<3;s++) cv = fmaf(nb[r][s], wsm[t*9+r*3+s], cv);
        g_xm9[((size_t)(n*9+t))*HWSZ + idx] = fmaf(nb[ii][jj], ctr, cv);
    }
}

// ---------------- xm25 = aff5(inp) + conv(xm9, d1) -----------------------------
// block (32,8); all 25 outputs per block; 4 px/thread (x = tx + 32k); tile 128x8
__global__ __launch_bounds__(256) void xm25_k(const float* __restrict__ d1)
{
    __shared__ float ti[12][132];       // inp halo (rows y0-2.., cols x0-2..)
    __shared__ float t9[2][10][132];    // xm9 halo, double buffered
    __shared__ float wsm[25*81];
    const int n = blockIdx.z;
    const int x0 = blockIdx.x*128, y0 = blockIdx.y*8;
    const int tid = threadIdx.y*32 + threadIdx.x;
    const int tx = threadIdx.x, ty = threadIdx.y;

    for (int i=tid;i<25*81;i+=256) wsm[i] = d1[i];
    for (int i=tid;i<12*132;i+=256){
        int yy=i/132, xx=i-yy*132;
        int gy=y0+yy-2, gx=x0+xx-2;
        ti[yy][xx] = ((unsigned)gy<HH && (unsigned)gx<WW) ? g_inp[(size_t)n*HWSZ + (size_t)gy*WW + gx] : 0.f;
    }
    // preload xm9 channel 0
    for (int i=tid;i<10*132;i+=256){
        int yy=i/132, xx=i-yy*132;
        int gy=y0+yy-1, gx=x0+xx-1;
        t9[0][yy][xx] = ((unsigned)gy<HH && (unsigned)gx<WW) ? g_xm9[((size_t)(n*9+0))*HWSZ + (size_t)gy*WW + gx] : 0.f;
    }
    __syncthreads();

    float acc[25][4];
    #pragma unroll
    for (int t=0;t<25;t++)
        #pragma unroll
        for (int k=0;k<4;k++) acc[t][k]=0.f;

    for (int c=0;c<9;c++){
        const int cur = c & 1;
        if (c+1 < 9){
            for (int i=tid;i<10*132;i+=256){
                int yy=i/132, xx=i-yy*132;
                int gy=y0+yy-1, gx=x0+xx-1;
                t9[cur^1][yy][xx] = ((unsigned)gy<HH && (unsigned)gx<WW) ? g_xm9[((size_t)(n*9+c+1))*HWSZ + (size_t)gy*WW + gx] : 0.f;
            }
        }
        #pragma unroll
        for (int r=0;r<3;r++)
        #pragma unroll
        for (int s=0;s<3;s++){
            float v[4];
            #pragma unroll
            for (int k=0;k<4;k++) v[k] = t9[cur][ty + r][tx + 32*k + s];
            #pragma unroll
            for (int t=0;t<25;t++){
                float wv = wsm[t*81 + c*9 + r*3 + s];
                #pragma unroll
                for (int k=0;k<4;k++) acc[t][k] = fmaf(wv, v[k], acc[t][k]);
            }
        }
        __syncthreads();
    }

    #pragma unroll
    for (int t=0;t<25;t++){
        const int ii = t/5, jj = t%5;
        #pragma unroll
        for (int k=0;k<4;k++){
            int lx = tx + 32*k;
            float ctr = ti[ty+2][lx+2];
            float aff = ti[ty+ii][lx+jj] * ctr;
            g_xm25[((size_t)(n*25+t))*HWSZ + (size_t)(y0+ty)*WW + x0 + lx] = aff + acc[t][k];
        }
    }
}

// ---------------- conv4d + affinity reduce + seg output ------------------------
__global__ __launch_bounds__(256) void final_k(const float* __restrict__ d4,
                                               float* __restrict__ segout)
{
    __shared__ float t25[25][10][34];
    __shared__ float ti[12][36];
    __shared__ float wsm[81];
    const int n = blockIdx.z;
    const int x0 = blockIdx.x*32, y0 = blockIdx.y*8;
    const int tid = threadIdx.y*32 + threadIdx.x;
    if (tid < 81) wsm[tid] = d4[tid];
    for (int i = tid; i < 25*340; i += 256){
        int c = i/340, rr = i - c*340, yy = rr/34, xx = rr%34;
        int gy=y0+yy-1, gx=x0+xx-1;
        t25[c][yy][xx] = ((unsigned)gy<HH && (unsigned)gx<WW) ? g_xm25[((size_t)(n*25+c))*HWSZ + gy*WW + gx] : 0.f;
    }
    for (int i=tid;i<432;i+=256){
        int yy=i/36, xx=i%36;
        int gy=y0+yy-2, gx=x0+xx-2;
        ti[yy][xx] = ((unsigned)gy<HH && (unsigned)gx<WW) ? g_inp[(size_t)n*HWSZ + gy*WW + gx] : 0.f;
    }
    __syncthreads();

    float kacc[25];
    #pragma unroll
    for (int t=0;t<25;t++) kacc[t]=0.f;

    #pragma unroll
    for (int r=0;r<3;r++)
    #pragma unroll
    for (int s=0;s<3;s++){
        float wv[9];
        #pragma unroll
        for (int p=0;p<3;p++)
        #pragma unroll
        for (int q=0;q<3;q++) wv[p*3+q] = wsm[((p*3+q)*3+r)*3 + s];
        float L[25];
        #pragma unroll
        for (int u=0;u<5;u++)
        #pragma unroll
        for (int v=0;v<5;v++) L[u*5+v] = t25[u*5+v][threadIdx.y+r][threadIdx.x+s];
        #pragma unroll
        for (int d=0;d<5;d++)
        #pragma unroll
        for (int e=0;e<5;e++)
        #pragma unroll
        for (int p=0;p<3;p++){
            int u = d-1+p; if (u < 0 || u > 4) continue;
            #pragma unroll
            for (int q=0;q<3;q++){
                int v = e-1+q; if (v < 0 || v > 4) continue;
                kacc[d*5+e] = fmaf(L[u*5+v], wv[p*3+q], kacc[d*5+e]);
            }
        }
    }
    float sum = 0.f;
    #pragma unroll
    for (int ii=0;ii<5;ii++)
    #pragma unroll
    for (int jj=0;jj<5;jj++)
        sum = fmaf(ti[threadIdx.y+ii][threadIdx.x+jj], kacc[ii*5+jj], sum);

    float o = sum / 25.0f;
    int idx = (y0+threadIdx.y)*WW + x0 + threadIdx.x;
    segout[((size_t)(n*2+0))*HWSZ + idx] = 1.0f - o;
    segout[((size_t)(n*2+1))*HWSZ + idx] = o;
}

// ---------------- top-k threshold: radix select on float keys ------------------
__device__ __forceinline__ unsigned f2key(float f){
    unsigned u = __float_as_uint(f);
    return (u & 0x80000000u) ? ~u : (u | 0x80000000u);
}
__device__ __forceinline__ float key2f(unsigned k){
    unsigned u = (k & 0x80000000u) ? (k & 0x7fffffffu) : ~k;
    return __uint_as_float(u);
}

__global__ void thr_init_k(const float* __restrict__ ratio)
{
    int t = threadIdx.x;
    unsigned* hflat = &g_hist[0][0];
    for (int i=t;i<4*256;i+=256) hflat[i]=0u;
    if (t < 4){
        int n = t >> 1;
        float fp = floorf(ratio[n]*(float)HWSZ);
        int k = (int)floorf(fp*0.1f);
        int idx = k-1; if (idx < 0) idx = 0;
        g_remain[t] = idx;
        g_prefix[t] = 0u;
    }
}

__global__ __launch_bounds__(256) void hist_k(const float* __restrict__ seg, int shift)
{
    __shared__ unsigned hh[256];
    const int j = blockIdx.y;
    hh[threadIdx.x]=0u;
    __syncthreads();
    unsigned pfx = g_prefix[j];
    unsigned mask = (shift==24) ? 0u : (0xFFFFFFFFu << (shift+8));
    const float* p = seg + (size_t)j*HWSZ;
    for (int i = blockIdx.x*256 + threadIdx.x; i < HWSZ; i += 64*256){
        unsigned key = f2key(p[i]);
        if ((key & mask) == pfx) atomicAdd(&hh[(key>>shift)&255u], 1u);
    }
    __syncthreads();
    if (hh[threadIdx.x]) atomicAdd(&g_hist[j][threadIdx.x], hh[threadIdx.x]);
}

__global__ void select_k(int shift, int last)
{
    int j = threadIdx.x;
    if (j >= 4) return;
    int rem = g_remain[j];
    unsigned pfx = g_prefix[j];
    int done = 0;
    for (int b=255;b>=0;b--){
        unsigned c = g_hist[j][b];
        if (!done){
            if ((int)c > rem){ pfx |= ((unsigned)b)<<shift; done=1; }
            else rem -= (int)c;
        }
        g_hist[j][b]=0u;
    }
    g_prefix[j]=pfx; g_remain[j]=rem;
    if (last) g_thr[j] = key2f(pfx);
}

__global__ __launch_bounds__(256) void erase_k(const float* __restrict__ seg,
                                               const float* __restrict__ x)
{
    int i = blockIdx.x*256 + threadIdx.x;
    if (i >= NHW) return;
    int n = i / HWSZ, r = i - n*HWSZ;
    float t0 = g_thr[n*2+0], t1 = g_thr[n*2+1];
    bool m = (seg[((size_t)(n*2+0))*HWSZ + r] > t0) || (seg[((size_t)(n*2+1))*HWSZ + r] > t1);
    #pragma unroll
    for (int c=0;c<3;c++)
        g_img2[((size_t)(n*3+c))*HWSZ + r] = m ? 0.f : x[((size_t)(n*3+c))*HWSZ + r];
}

// ---------------- host orchestration -------------------------------------------
struct Ptrs { float *feat, *aux, *auxb1, *z, *scale1, *shift1, *scale2, *shift2; };

static void run_pipeline(const float* img, float* seg_out,
                         const float* w1, const float* wa, const float* wout,
                         const float* b1w, const float* b1g, const float* b1b,
                         const float* b2w, const float* b2g, const float* b2b,
                         const float* d0w, const float* d1w, const float* d4w,
                         const Ptrs& P)
{
    dim3 blk(32,8);
    dim3 gconv(8,16,NB*4);   // 64x32 tiles
    conv3x3_f2<3,true ><<<gconv, blk>>>(img,    w1,  P.feat,  4);
    conv3x3_f2<3,true ><<<gconv, blk>>>(img,    wa,  P.aux,   4);
    conv3x3_f2<32,false><<<gconv, blk>>>(P.aux, b1w, P.auxb1, 4);
    stats1_k<<<dim3(PARTS,32), 256>>>(P.auxb1, 32);
    stats2_k<<<32,128>>>(b1g, b1b, P.scale1, P.shift1);
    b2_k<<<(NHW+255)/256, 256>>>(b2w);
    stats1_k<<<dim3(PARTS,1), 256>>>(P.z, 1);
    stats2_k<<<1,128>>>(b2g, b2b, P.scale2, P.shift2);
    wout_inp_k<<<dim3(16,16,NB), blk>>>(P.feat, wout);
    xm9_k<<<dim3(16,64,NB), blk>>>(d0w);
    xm25_k<<<dim3(4,64,NB), blk>>>(d1w);
    final_k<<<dim3(16,64,NB), blk>>>(d4w, seg_out);
}

extern "C" void kernel_launch(void* const* d_in, const int* in_sizes, int n_in,
                              void* d_out, int out_size)
{
    const float* x     = (const float*)d_in[0];
    const float* ratio = (const float*)d_in[1];
    const float* w1    = (const float*)d_in[2];
    const float* wa    = (const float*)d_in[3];
    const float* wout  = (const float*)d_in[4];
    const float* b1w   = (const float*)d_in[5];
    const float* b1g   = (const float*)d_in[6];
    const float* b1b   = (const float*)d_in[7];
    const float* b2w   = (const float*)d_in[8];
    const float* b2g   = (const float*)d_in[9];
    const float* b2b   = (const float*)d_in[10];
    const float* d0w   = (const float*)d_in[11];
    const float* d1w   = (const float*)d_in[12];
    const float* d4w   = (const float*)d_in[13];
    float* out = (float*)d_out;

    Ptrs P;
    void* p;
    cudaGetSymbolAddress(&p, g_feat);   P.feat   = (float*)p;
    cudaGetSymbolAddress(&p, g_aux);    P.aux    = (float*)p;
    cudaGetSymbolAddress(&p, g_auxb1);  P.auxb1  = (float*)p;
    cudaGetSymbolAddress(&p, g_z);      P.z      = (float*)p;
    cudaGetSymbolAddress(&p, g_scale1); P.scale1 = (float*)p;
    cudaGetSymbolAddress(&p, g_shift1); P.shift1 = (float*)p;
    cudaGetSymbolAddress(&p, g_scale2); P.scale2 = (float*)p;
    cudaGetSymbolAddress(&p, g_shift2); P.shift2 = (float*)p;
    float* img2; cudaGetSymbolAddress(&p, g_img2); img2 = (float*)p;

    // pipeline 1 -> x1 (first half of output)
    run_pipeline(x, out, w1, wa, wout, b1w, b1g, b1b, b2w, b2g, b2b,
                 d0w, d1w, d4w, P);

    // erasing: per-(n,c) radix select of the idx-th largest seg value
    thr_init_k<<<1,256>>>(ratio);
    for (int pass=0; pass<4; ++pass){
        int shift = 24 - 8*pass;
        hist_k<<<dim3(64,4), 256>>>(out, shift);
        select_k<<<1,4>>>(shift, pass==3 ? 1 : 0);
    }
    erase_k<<<(NHW+255)/256, 256>>>(out, x);

    // pipeline 2 -> x2 (second half of output)
    run_pipeline(img2, out + (size_t)NB*2*HWSZ, w1, wa, wout,
                 b1w, b1g, b1b, b2w, b2g, b2b, d0w, d1w, d4w, P);
}

// round 4
// speedup vs baseline: 1.1793x; 1.1793x over previous
#include <cuda_runtime.h>
#include <math.h>

#define HH 512
#define WW 512
#define NB 2
#define HWSZ (HH*WW)          // 262144
#define NHW (NB*HWSZ)         // 524288
#define PARTS 128

// ---------------- scratch (device globals; no allocation allowed) -------------
__device__ float g_feat [NB*32*HWSZ];
__device__ float g_aux  [NB*32*HWSZ];
__device__ float g_auxb1[NB*32*HWSZ];
__device__ float g_z    [NHW];
__device__ float g_inp  [NHW];
__device__ float g_xm9  [NB*9*HWSZ];
__device__ float g_xm25 [NB*25*HWSZ];
__device__ float g_img2 [NB*3*HWSZ];
__device__ float g_part [32*PARTS*2];
__device__ float g_scale1[32], g_shift1[32];
__device__ float g_scale2[1],  g_shift2[1];
__device__ unsigned g_hist[4][256];
__device__ unsigned g_prefix[4];
__device__ int      g_remain[4];
__device__ float    g_thr[4];

// ---------------- 3x3 conv: 8 oc x 8 rows per thread, tile 32w x 64h ----------
// block (32,8); double-buffered input tile; scalar FFMA (f32x2 regressed: RF banks)
template<int IC, bool RELU>
__global__ __launch_bounds__(256) void conv3x3_k(
    const float* __restrict__ in, const float* __restrict__ wt,
    float* __restrict__ out, int ocGroups)
{
    __shared__ float tile[2][66][34];
    __shared__ float wsm[8*IC*9];
    const int tid = threadIdx.y*32 + threadIdx.x;
    const int tx = threadIdx.x, ty = threadIdx.y;
    const int grp = blockIdx.z % ocGroups;
    const int n   = blockIdx.z / ocGroups;
    const int OC  = ocGroups*8;
    const int oc0 = grp*8;
    const int x0 = blockIdx.x*32, y0 = blockIdx.y*64;

    for (int i = tid; i < 8*IC*9; i += 256) wsm[i] = wt[oc0*IC*9 + i];

    // load channel 0 into buffer 0
    {
        const float* src = in + ((size_t)(n*IC))*HWSZ;
        for (int i = tid; i < 66*34; i += 256){
            int yy = i/34, xx = i - yy*34;
            int gy = y0+yy-1, gx = x0+xx-1;
            tile[0][yy][xx] = ((unsigned)gy<HH && (unsigned)gx<WW) ? src[(size_t)gy*WW+gx] : 0.f;
        }
    }
    __syncthreads();

    float acc[8][8];
    #pragma unroll
    for (int o=0;o<8;o++)
        #pragma unroll
        for (int k=0;k<8;k++) acc[o][k]=0.f;

    for (int c = 0; c < IC; c++){
        const int cur = c & 1;
        if (c+1 < IC){
            const float* src = in + ((size_t)(n*IC + c+1))*HWSZ;
            for (int i = tid; i < 66*34; i += 256){
                int yy = i/34, xx = i - yy*34;
                int gy = y0+yy-1, gx = x0+xx-1;
                tile[cur^1][yy][xx] = ((unsigned)gy<HH && (unsigned)gx<WW) ? src[(size_t)gy*WW+gx] : 0.f;
            }
        }
        #pragma unroll
        for (int r=0;r<3;r++){
            float wv[8][3];
            #pragma unroll
            for (int o=0;o<8;o++)
            #pragma unroll
            for (int s=0;s<3;s++)
                wv[o][s] = wsm[(o*IC+c)*9 + r*3 + s];
            #pragma unroll
            for (int k=0;k<8;k++){
                const int row = ty + 8*k + r;
                float v0 = tile[cur][row][tx];
                float v1 = tile[cur][row][tx+1];
                float v2 = tile[cur][row][tx+2];
                #pragma unroll
                for (int o=0;o<8;o++){
                    acc[o][k] = fmaf(wv[o][0], v0, acc[o][k]);
                    acc[o][k] = fmaf(wv[o][1], v1, acc[o][k]);
                    acc[o][k] = fmaf(wv[o][2], v2, acc[o][k]);
                }
            }
        }
        __syncthreads();
    }

    #pragma unroll
    for (int o=0;o<8;o++)
    #pragma unroll
    for (int k=0;k<8;k++){
        float v = acc[o][k];
        if (RELU) v = fmaxf(v, 0.f);
        out[((size_t)(n*OC + oc0 + o))*HWSZ + (size_t)(y0+ty+8*k)*WW + x0 + tx] = v;
    }
}

// ---------------- x1 = conv(feat, w_out) ; inp = x1 + relu(bn(z)) --------------
__global__ __launch_bounds__(256) void wout_inp_k(
    const float* __restrict__ feat, const float* __restrict__ wt)
{
    __shared__ float tile[34][34];
    __shared__ float wsm[32*9];
    const int tid = threadIdx.y*32 + threadIdx.x;
    const int n = blockIdx.z;
    for (int i = tid; i < 288; i += 256) wsm[i] = wt[i];
    const int x0 = blockIdx.x*32, y0 = blockIdx.y*32;
    float acc[4] = {0.f,0.f,0.f,0.f};
    for (int c = 0; c < 32; c++) {
        __syncthreads();
        for (int i = tid; i < 34*34; i += 256) {
            int yy = i/34, xx = i%34;
            int gy = y0+yy-1, gx = x0+xx-1;
            float v = 0.f;
            if ((unsigned)gy < HH && (unsigned)gx < WW)
                v = feat[((size_t)(n*32 + c))*HWSZ + gy*WW + gx];
            tile[yy][xx] = v;
        }
        __syncthreads();
        #pragma unroll
        for (int r=0;r<3;r++)
        #pragma unroll
        for (int s=0;s<3;s++) {
            float w = wsm[c*9 + r*3 + s];
            #pragma unroll
            for (int k=0;k<4;k++)
                acc[k] = fmaf(w, tile[threadIdx.y + 8*k + r][threadIdx.x + s], acc[k]);
        }
    }
    float s2 = g_scale2[0], h2 = g_shift2[0];
    #pragma unroll
    for (int k=0;k<4;k++) {
        int idx = (y0+threadIdx.y+8*k)*WW + x0 + threadIdx.x;
        float zz = g_z[(size_t)n*HWSZ + idx];
        g_inp[(size_t)n*HWSZ + idx] = acc[k] + fmaxf(zz*s2 + h2, 0.f);
    }
}

// ---------------- batchnorm stats for 32-ch (deterministic two-stage) ----------
__global__ __launch_bounds__(256) void stats1_k(const float* __restrict__ in, int C)
{
    const int c = blockIdx.y, p = blockIdx.x;
    const int chunk = NHW / PARTS;
    const int base = p*chunk;
    float s = 0.f, q = 0.f;
    for (int i = base + threadIdx.x; i < base + chunk; i += 256) {
        int nn = i / HWSZ, r = i - nn*HWSZ;
        float v = in[((size_t)(nn*C + c))*HWSZ + r];
        s += v; q += v*v;
    }
    __shared__ float ss[256], qq[256];
    ss[threadIdx.x]=s; qq[threadIdx.x]=q;
    __syncthreads();
    for (int o=128;o>0;o>>=1){
        if (threadIdx.x < o){ ss[threadIdx.x]+=ss[threadIdx.x+o]; qq[threadIdx.x]+=qq[threadIdx.x+o]; }
        __syncthreads();
    }
    if (threadIdx.x==0){
        g_part[(c*PARTS+p)*2+0]=ss[0];
        g_part[(c*PARTS+p)*2+1]=qq[0];
    }
}

__global__ void stats2_k(const float* __restrict__ g, const float* __restrict__ b,
                         float* __restrict__ scale, float* __restrict__ shift)
{
    const int c = blockIdx.x;
    __shared__ float ss[128], qq[128];
    ss[threadIdx.x] = g_part[(c*PARTS+threadIdx.x)*2+0];
    qq[threadIdx.x] = g_part[(c*PARTS+threadIdx.x)*2+1];
    __syncthreads();
    for (int o=64;o>0;o>>=1){
        if (threadIdx.x < o){ ss[threadIdx.x]+=ss[threadIdx.x+o]; qq[threadIdx.x]+=qq[threadIdx.x+o]; }
        __syncthreads();
    }
    if (threadIdx.x==0){
        float mean = ss[0]/(float)NHW;
        float var  = qq[0]/(float)NHW - mean*mean;
        float sc = g[c]*rsqrtf(var + 1e-5f);
        scale[c]=sc; shift[c]=b[c]-mean*sc;
    }
}

// ---------------- z = sum_c relu(bn(auxb1_c)) * b2w_c  (+fused z partial stats)
__global__ __launch_bounds__(256) void b2_k(const float* __restrict__ w2)
{
    __shared__ float s[32], h[32], ww[32];
    if (threadIdx.x < 32){ s[threadIdx.x]=g_scale1[threadIdx.x];
                           h[threadIdx.x]=g_shift1[threadIdx.x];
                           ww[threadIdx.x]=w2[threadIdx.x]; }
    __syncthreads();
    int i = blockIdx.x*256 + threadIdx.x;
    int n = i / HWSZ, r = i - n*HWSZ;
    float acc = 0.f;
    #pragma unroll
    for (int c=0;c<32;c++){
        float v = g_auxb1[((size_t)(n*32+c))*HWSZ + r];
        acc += fmaxf(v*s[c]+h[c], 0.f)*ww[c];
    }
    g_z[i] = acc;
    // deterministic per-block partial sums for z batchnorm
    __shared__ float ss[256], qq[256];
    ss[threadIdx.x]=acc; qq[threadIdx.x]=acc*acc;
    __syncthreads();
    for (int o=128;o>0;o>>=1){
        if (threadIdx.x < o){ ss[threadIdx.x]+=ss[threadIdx.x+o]; qq[threadIdx.x]+=qq[threadIdx.x+o]; }
        __syncthreads();
    }
    if (threadIdx.x==0){
        g_part[blockIdx.x*2+0]=ss[0];
        g_part[blockIdx.x*2+1]=qq[0];
    }
}

// reduce the 2048 b2 partials -> scale2/shift2
__global__ __launch_bounds__(256) void stats2z_k(const float* __restrict__ g,
                                                 const float* __restrict__ b)
{
    float s=0.f, q=0.f;
    for (int j = threadIdx.x; j < NHW/256; j += 256){
        s += g_part[j*2+0];
        q += g_part[j*2+1];
    }
    __shared__ float ss[256], qq[256];
    ss[threadIdx.x]=s; qq[threadIdx.x]=q;
    __syncthreads();
    for (int o=128;o>0;o>>=1){
        if (threadIdx.x < o){ ss[threadIdx.x]+=ss[threadIdx.x+o]; qq[threadIdx.x]+=qq[threadIdx.x+o]; }
        __syncthreads();
    }
    if (threadIdx.x==0){
        float mean = ss[0]/(float)NHW;
        float var  = qq[0]/(float)NHW - mean*mean;
        float sc = g[0]*rsqrtf(var + 1e-5f);
        g_scale2[0]=sc; g_shift2[0]=b[0]-mean*sc;
    }
}

// ---------------- xm9 = aff3(inp) + conv(inp, d0) ------------------------------
__global__ __launch_bounds__(256) void xm9_k(const float* __restrict__ d0)
{
    __shared__ float tile[10][34];
    __shared__ float wsm[81];
    const int n = blockIdx.z;
    const int x0 = blockIdx.x*32, y0 = blockIdx.y*8;
    const int tid = threadIdx.y*32 + threadIdx.x;
    if (tid < 81) wsm[tid] = d0[tid];
    for (int i = tid; i < 340; i += 256){
        int yy=i/34, xx=i%34;
        int gy=y0+yy-1, gx=x0+xx-1;
        tile[yy][xx] = ((unsigned)gy<HH && (unsigned)gx<WW) ? g_inp[(size_t)n*HWSZ + gy*WW + gx] : 0.f;
    }
    __syncthreads();
    float nb[3][3];
    #pragma unroll
    for (int r=0;r<3;r++)
    #pragma unroll
    for (int s=0;s<3;s++) nb[r][s] = tile[threadIdx.y+r][threadIdx.x+s];
    float ctr = nb[1][1];
    int idx = (y0+threadIdx.y)*WW + x0 + threadIdx.x;
    #pragma unroll
    for (int t=0;t<9;t++){
        int ii=t/3, jj=t%3;
        float cv=0.f;
        #pragma unroll
        for (int r=0;r<3;r++)
        #pragma unroll
        for (int s=0;s<3;s++) cv = fmaf(nb[r][s], wsm[t*9+r*3+s], cv);
        g_xm9[((size_t)(n*9+t))*HWSZ + idx] = fmaf(nb[ii][jj], ctr, cv);
    }
}

// ---------------- xm25 = aff5(inp) + conv(xm9, d1) -----------------------------
// block (32,8); all 25 outputs per block; 4 px/thread (x = tx + 32k); tile 128x8
__global__ __launch_bounds__(256) void xm25_k(const float* __restrict__ d1)
{
    __shared__ float ti[12][132];       // inp halo (rows y0-2.., cols x0-2..)
    __shared__ float t9[2][10][132];    // xm9 halo, double buffered
    __shared__ float wsm[25*81];
    const int n = blockIdx.z;
    const int x0 = blockIdx.x*128, y0 = blockIdx.y*8;
    const int tid = threadIdx.y*32 + threadIdx.x;
    const int tx = threadIdx.x, ty = threadIdx.y;

    for (int i=tid;i<25*81;i+=256) wsm[i] = d1[i];
    for (int i=tid;i<12*132;i+=256){
        int yy=i/132, xx=i-yy*132;
        int gy=y0+yy-2, gx=x0+xx-2;
        ti[yy][xx] = ((unsigned)gy<HH && (unsigned)gx<WW) ? g_inp[(size_t)n*HWSZ + (size_t)gy*WW + gx] : 0.f;
    }
    for (int i=tid;i<10*132;i+=256){
        int yy=i/132, xx=i-yy*132;
        int gy=y0+yy-1, gx=x0+xx-1;
        t9[0][yy][xx] = ((unsigned)gy<HH && (unsigned)gx<WW) ? g_xm9[((size_t)(n*9+0))*HWSZ + (size_t)gy*WW + gx] : 0.f;
    }
    __syncthreads();

    float acc[25][4];
    #pragma unroll
    for (int t=0;t<25;t++)
        #pragma unroll
        for (int k=0;k<4;k++) acc[t][k]=0.f;

    for (int c=0;c<9;c++){
        const int cur = c & 1;
        if (c+1 < 9){
            for (int i=tid;i<10*132;i+=256){
                int yy=i/132, xx=i-yy*132;
                int gy=y0+yy-1, gx=x0+xx-1;
                t9[cur^1][yy][xx] = ((unsigned)gy<HH && (unsigned)gx<WW) ? g_xm9[((size_t)(n*9+c+1))*HWSZ + (size_t)gy*WW + gx] : 0.f;
            }
        }
        #pragma unroll
        for (int r=0;r<3;r++)
        #pragma unroll
        for (int s=0;s<3;s++){
            float v[4];
            #pragma unroll
            for (int k=0;k<4;k++) v[k] = t9[cur][ty + r][tx + 32*k + s];
            #pragma unroll
            for (int t=0;t<25;t++){
                float wv = wsm[t*81 + c*9 + r*3 + s];
                #pragma unroll
                for (int k=0;k<4;k++) acc[t][k] = fmaf(wv, v[k], acc[t][k]);
            }
        }
        __syncthreads();
    }

    #pragma unroll
    for (int t=0;t<25;t++){
        const int ii = t/5, jj = t%5;
        #pragma unroll
        for (int k=0;k<4;k++){
            int lx = tx + 32*k;
            float ctr = ti[ty+2][lx+2];
            float aff = ti[ty+ii][lx+jj] * ctr;
            g_xm25[((size_t)(n*25+t))*HWSZ + (size_t)(y0+ty)*WW + x0 + lx] = aff + acc[t][k];
        }
    }
}

// ---------------- conv4d + affinity reduce + seg output ------------------------
__global__ __launch_bounds__(256) void final_k(const float* __restrict__ d4,
                                               float* __restrict__ segout)
{
    __shared__ float t25[25][10][34];
    __shared__ float ti[12][36];
    __shared__ float wsm[81];
    const int n = blockIdx.z;
    const int x0 = blockIdx.x*32, y0 = blockIdx.y*8;
    const int tid = threadIdx.y*32 + threadIdx.x;
    if (tid < 81) wsm[tid] = d4[tid];
    for (int i = tid; i < 25*340; i += 256){
        int c = i/340, rr = i - c*340, yy = rr/34, xx = rr%34;
        int gy=y0+yy-1, gx=x0+xx-1;
        t25[c][yy][xx] = ((unsigned)gy<HH && (unsigned)gx<WW) ? g_xm25[((size_t)(n*25+c))*HWSZ + gy*WW + gx] : 0.f;
    }
    for (int i=tid;i<432;i+=256){
        int yy=i/36, xx=i%36;
        int gy=y0+yy-2, gx=x0+xx-2;
        ti[yy][xx] = ((unsigned)gy<HH && (unsigned)gx<WW) ? g_inp[(size_t)n*HWSZ + gy*WW + gx] : 0.f;
    }
    __syncthreads();

    float kacc[25];
    #pragma unroll
    for (int t=0;t<25;t++) kacc[t]=0.f;

    #pragma unroll
    for (int r=0;r<3;r++)
    #pragma unroll
    for (int s=0;s<3;s++){
        float wv[9];
        #pragma unroll
        for (int p=0;p<3;p++)
        #pragma unroll
        for (int q=0;q<3;q++) wv[p*3+q] = wsm[((p*3+q)*3+r)*3 + s];
        float L[25];
        #pragma unroll
        for (int u=0;u<5;u++)
        #pragma unroll
        for (int v=0;v<5;v++) L[u*5+v] = t25[u*5+v][threadIdx.y+r][threadIdx.x+s];
        #pragma unroll
        for (int d=0;d<5;d++)
        #pragma unroll
        for (int e=0;e<5;e++)
        #pragma unroll
        for (int p=0;p<3;p++){
            int u = d-1+p; if (u < 0 || u > 4) continue;
            #pragma unroll
            for (int q=0;q<3;q++){
                int v = e-1+q; if (v < 0 || v > 4) continue;
                kacc[d*5+e] = fmaf(L[u*5+v], wv[p*3+q], kacc[d*5+e]);
            }
        }
    }
    float sum = 0.f;
    #pragma unroll
    for (int ii=0;ii<5;ii++)
    #pragma unroll
    for (int jj=0;jj<5;jj++)
        sum = fmaf(ti[threadIdx.y+ii][threadIdx.x+jj], kacc[ii*5+jj], sum);

    float o = sum / 25.0f;
    int idx = (y0+threadIdx.y)*WW + x0 + threadIdx.x;
    segout[((size_t)(n*2+0))*HWSZ + idx] = 1.0f - o;
    segout[((size_t)(n*2+1))*HWSZ + idx] = o;
}

// ---------------- top-k threshold: radix select on float keys ------------------
__device__ __forceinline__ unsigned f2key(float f){
    unsigned u = __float_as_uint(f);
    return (u & 0x80000000u) ? ~u : (u | 0x80000000u);
}
__device__ __forceinline__ float key2f(unsigned k){
    unsigned u = (k & 0x80000000u) ? (k & 0x7fffffffu) : ~k;
    return __uint_as_float(u);
}

__global__ void thr_init_k(const float* __restrict__ ratio)
{
    int t = threadIdx.x;
    unsigned* hflat = &g_hist[0][0];
    for (int i=t;i<4*256;i+=256) hflat[i]=0u;
    if (t < 4){
        int n = t >> 1;
        float fp = floorf(ratio[n]*(float)HWSZ);
        int k = (int)floorf(fp*0.1f);
        int idx = k-1; if (idx < 0) idx = 0;
        g_remain[t] = idx;
        g_prefix[t] = 0u;
    }
}

__global__ __launch_bounds__(256) void hist_k(const float* __restrict__ seg, int shift)
{
    __shared__ unsigned hh[256];
    const int j = blockIdx.y;
    hh[threadIdx.x]=0u;
    __syncthreads();
    unsigned pfx = g_prefix[j];
    unsigned mask = (shift==24) ? 0u : (0xFFFFFFFFu << (shift+8));
    const float* p = seg + (size_t)j*HWSZ;
    for (int i = blockIdx.x*256 + threadIdx.x; i < HWSZ; i += 64*256){
        unsigned key = f2key(p[i]);
        if ((key & mask) == pfx) atomicAdd(&hh[(key>>shift)&255u], 1u);
    }
    __syncthreads();
    if (hh[threadIdx.x]) atomicAdd(&g_hist[j][threadIdx.x], hh[threadIdx.x]);
}

__global__ void select_k(int shift, int last)
{
    int j = threadIdx.x;
    if (j >= 4) return;
    int rem = g_remain[j];
    unsigned pfx = g_prefix[j];
    int done = 0;
    for (int b=255;b>=0;b--){
        unsigned c = g_hist[j][b];
        if (!done){
            if ((int)c > rem){ pfx |= ((unsigned)b)<<shift; done=1; }
            else rem -= (int)c;
        }
        g_hist[j][b]=0u;
    }
    g_prefix[j]=pfx; g_remain[j]=rem;
    if (last) g_thr[j] = key2f(pfx);
}

__global__ __launch_bounds__(256) void erase_k(const float* __restrict__ seg,
                                               const float* __restrict__ x)
{
    int i = blockIdx.x*256 + threadIdx.x;
    if (i >= NHW) return;
    int n = i / HWSZ, r = i - n*HWSZ;
    float t0 = g_thr[n*2+0], t1 = g_thr[n*2+1];
    bool m = (seg[((size_t)(n*2+0))*HWSZ + r] > t0) || (seg[((size_t)(n*2+1))*HWSZ + r] > t1);
    #pragma unroll
    for (int c=0;c<3;c++)
        g_img2[((size_t)(n*3+c))*HWSZ + r] = m ? 0.f : x[((size_t)(n*3+c))*HWSZ + r];
}

// ---------------- host orchestration -------------------------------------------
struct Ptrs { float *feat, *aux, *auxb1, *z, *scale1, *shift1; };

static void run_pipeline(const float* img, float* seg_out,
                         const float* w1, const float* wa, const float* wout,
                         const float* b1w, const float* b1g, const float* b1b,
                         const float* b2w, const float* b2g, const float* b2b,
                         const float* d0w, const float* d1w, const float* d4w,
                         const Ptrs& P)
{
    dim3 blk(32,8);
    dim3 gconv(16,8,NB*4);   // 32x64 tiles
    conv3x3_k<3,true ><<<gconv, blk>>>(img,    w1,  P.feat,  4);
    conv3x3_k<3,true ><<<gconv, blk>>>(img,    wa,  P.aux,   4);
    conv3x3_k<32,false><<<gconv, blk>>>(P.aux, b1w, P.auxb1, 4);
    stats1_k<<<dim3(PARTS,32), 256>>>(P.auxb1, 32);
    stats2_k<<<32,128>>>(b1g, b1b, P.scale1, P.shift1);
    b2_k<<<NHW/256, 256>>>(b2w);
    stats2z_k<<<1,256>>>(b2g, b2b);
    wout_inp_k<<<dim3(16,16,NB), blk>>>(P.feat, wout);
    xm9_k<<<dim3(16,64,NB), blk>>>(d0w);
    xm25_k<<<dim3(4,64,NB), blk>>>(d1w);
    final_k<<<dim3(16,64,NB), blk>>>(d4w, seg_out);
}

extern "C" void kernel_launch(void* const* d_in, const int* in_sizes, int n_in,
                              void* d_out, int out_size)
{
    const float* x     = (const float*)d_in[0];
    const float* ratio = (const float*)d_in[1];
    const float* w1    = (const float*)d_in[2];
    const float* wa    = (const float*)d_in[3];
    const float* wout  = (const float*)d_in[4];
    const float* b1w   = (const float*)d_in[5];
    const float* b1g   = (const float*)d_in[6];
    const float* b1b   = (const float*)d_in[7];
    const float* b2w   = (const float*)d_in[8];
    const float* b2g   = (const float*)d_in[9];
    const float* b2b   = (const float*)d_in[10];
    const float* d0w   = (const float*)d_in[11];
    const float* d1w   = (const float*)d_in[12];
    const float* d4w   = (const float*)d_in[13];
    float* out = (float*)d_out;

    Ptrs P;
    void* p;
    cudaGetSymbolAddress(&p, g_feat);   P.feat   = (float*)p;
    cudaGetSymbolAddress(&p, g_aux);    P.aux    = (float*)p;
    cudaGetSymbolAddress(&p, g_auxb1);  P.auxb1  = (float*)p;
    cudaGetSymbolAddress(&p, g_z);      P.z      = (float*)p;
    cudaGetSymbolAddress(&p, g_scale1); P.scale1 = (float*)p;
    cudaGetSymbolAddress(&p, g_shift1); P.shift1 = (float*)p;
    float* img2; cudaGetSymbolAddress(&p, g_img2); img2 = (float*)p;

    // pipeline 1 -> x1 (first half of output)
    run_pipeline(x, out, w1, wa, wout, b1w, b1g, b1b, b2w, b2g, b2b,
                 d0w, d1w, d4w, P);

    // erasing: per-(n,c) radix select of the idx-th largest seg value
    thr_init_k<<<1,256>>>(ratio);
    for (int pass=0; pass<4; ++pass){
        int shift = 24 - 8*pass;
        hist_k<<<dim3(64,4), 256>>>(out, shift);
        select_k<<<1,4>>>(shift, pass==3 ? 1 : 0);
    }
    erase_k<<<(NHW+255)/256, 256>>>(out, x);

    // pipeline 2 -> x2 (second half of output)
    run_pipeline(img2, out + (size_t)NB*2*HWSZ, w1, wa, wout,
                 b1w, b1g, b1b, b2w, b2g, b2b, d0w, d1w, d4w, P);
}

// round 5
// speedup vs baseline: 1.5771x; 1.3373x over previous
#include <cuda_runtime.h>
#include <math.h>

#define HH 512
#define WW 512
#define NB 2
#define HWSZ (HH*WW)          // 262144
#define NHW (NB*HWSZ)         // 524288

// ---------------- scratch (device globals; no allocation allowed) -------------
__device__ float g_feat [NB*32*HWSZ];
__device__ float g_aux  [NB*32*HWSZ];
__device__ float g_auxb1[NB*32*HWSZ];
__device__ float g_z    [NHW];
__device__ float g_inp  [NHW];
__device__ float g_xm9  [NB*9*HWSZ];
__device__ float g_xm25 [NB*25*HWSZ];
__device__ float g_img2 [NB*3*HWSZ];
__device__ float g_part [32*256*2];
__device__ float g_scale1[32], g_shift1[32];
__device__ float g_scale2[1],  g_shift2[1];
__device__ unsigned g_hist[4][256];
__device__ unsigned g_prefix[4];
__device__ int      g_remain[4];
__device__ float    g_thr[4];

// ---------------- 3x3 conv: 8 oc x 8 rows/thread, tile 32w x 64h ---------------
// block (32,8); reg-staged prefetch: LDG->regs, FMA on cur buf, STS->alt, sync.
// STATS: fused deterministic per-block BN partial sums (pre-activation outputs).
template<int IC, bool RELU, bool STATS>
__global__ __launch_bounds__(256) void conv3x3_k(
    const float* __restrict__ in, const float* __restrict__ wt,
    float* __restrict__ out, int ocGroups)
{
    __shared__ float tile[2][66][34];
    __shared__ float wsm[8*IC*9];
    const int tid = threadIdx.y*32 + threadIdx.x;
    const int tx = threadIdx.x, ty = threadIdx.y;
    const int grp = blockIdx.z % ocGroups;
    const int n   = blockIdx.z / ocGroups;
    const int OC  = ocGroups*8;
    const int oc0 = grp*8;
    const int x0 = blockIdx.x*32, y0 = blockIdx.y*64;
    const int TSZ = 66*34;      // 2244
    const int NLD = 9;          // ceil(2244/256)

    for (int i = tid; i < 8*IC*9; i += 256) wsm[i] = wt[oc0*IC*9 + i];

    // precompute staging offsets + validity
    int off[NLD]; unsigned vmask = 0u;
    #pragma unroll
    for (int j=0;j<NLD;j++){
        int i = tid + j*256;
        int yy = i/34, xx = i - yy*34;
        int gy = y0+yy-1, gx = x0+xx-1;
        bool v = (i < TSZ) && ((unsigned)gy < HH) && ((unsigned)gx < WW);
        off[j] = v ? (gy*WW + gx) : 0;
        if (v) vmask |= (1u<<j);
    }

    // load channel 0 into buffer 0
    {
        const float* src = in + (size_t)(n*IC)*HWSZ;
        float rld[NLD];
        #pragma unroll
        for (int j=0;j<NLD;j++) rld[j] = ((vmask>>j)&1u) ? src[off[j]] : 0.f;
        float* tb = &tile[0][0][0];
        #pragma unroll
        for (int j=0;j<NLD;j++){ int i = tid + j*256; if (i < TSZ) tb[i] = rld[j]; }
    }
    __syncthreads();

    float acc[8][8];
    #pragma unroll
    for (int o=0;o<8;o++)
        #pragma unroll
        for (int k=0;k<8;k++) acc[o][k]=0.f;

    for (int c = 0; c < IC; c++){
        const int cur = c & 1;
        float rld[NLD];
        if (c+1 < IC){
            const float* src = in + (size_t)(n*IC + c+1)*HWSZ;
            #pragma unroll
            for (int j=0;j<NLD;j++) rld[j] = ((vmask>>j)&1u) ? src[off[j]] : 0.f;
        }
        #pragma unroll
        for (int r=0;r<3;r++){
            float wv[8][3];
            #pragma unroll
            for (int o=0;o<8;o++)
            #pragma unroll
            for (int s=0;s<3;s++)
                wv[o][s] = wsm[(o*IC+c)*9 + r*3 + s];
            #pragma unroll
            for (int k=0;k<8;k++){
                const int row = ty + 8*k + r;
                float v0 = tile[cur][row][tx];
                float v1 = tile[cur][row][tx+1];
                float v2 = tile[cur][row][tx+2];
                #pragma unroll
                for (int o=0;o<8;o++){
                    acc[o][k] = fmaf(wv[o][0], v0, acc[o][k]);
                    acc[o][k] = fmaf(wv[o][1], v1, acc[o][k]);
                    acc[o][k] = fmaf(wv[o][2], v2, acc[o][k]);
                }
            }
        }
        if (c+1 < IC){
            float* tb = &tile[cur^1][0][0];
            #pragma unroll
            for (int j=0;j<NLD;j++){ int i = tid + j*256; if (i < TSZ) tb[i] = rld[j]; }
        }
        __syncthreads();
    }

    #pragma unroll
    for (int o=0;o<8;o++)
    #pragma unroll
    for (int k=0;k<8;k++){
        float v = acc[o][k];
        if (RELU) v = fmaxf(v, 0.f);
        out[((size_t)(n*OC + oc0 + o))*HWSZ + (size_t)(y0+ty+8*k)*WW + x0 + tx] = v;
    }

    if (STATS){
        // deterministic per-block partials: sum / sumsq over this block's outputs
        float* red = &tile[0][0][0];   // reuse smem (all FMAs done; sync above)
        float s[8], q[8];
        #pragma unroll
        for (int o=0;o<8;o++){
            float sv=0.f, qv=0.f;
            #pragma unroll
            for (int k=0;k<8;k++){ float v=acc[o][k]; sv+=v; qv=fmaf(v,v,qv); }
            #pragma unroll
            for (int d=16; d>0; d>>=1){
                sv += __shfl_down_sync(0xffffffffu, sv, d);
                qv += __shfl_down_sync(0xffffffffu, qv, d);
            }
            s[o]=sv; q[o]=qv;
        }
        if (tx == 0){
            #pragma unroll
            for (int o=0;o<8;o++){ red[o*8+ty]=s[o]; red[64+o*8+ty]=q[o]; }
        }
        __syncthreads();
        if (tid < 8){
            float S=0.f, Q=0.f;
            #pragma unroll
            for (int w=0;w<8;w++){ S+=red[tid*8+w]; Q+=red[64+tid*8+w]; }
            int p = (n*gridDim.y + blockIdx.y)*gridDim.x + blockIdx.x;  // < 256
            g_part[((oc0+tid)*256+p)*2+0] = S;
            g_part[((oc0+tid)*256+p)*2+1] = Q;
        }
    }
}

// ---------------- reduce conv32 partials -> scale1/shift1 ----------------------
__global__ __launch_bounds__(256) void stats2_k(const float* __restrict__ g,
                                                const float* __restrict__ b)
{
    const int c = blockIdx.x;
    __shared__ float ss[256], qq[256];
    ss[threadIdx.x] = g_part[(c*256+threadIdx.x)*2+0];
    qq[threadIdx.x] = g_part[(c*256+threadIdx.x)*2+1];
    __syncthreads();
    for (int o=128;o>0;o>>=1){
        if (threadIdx.x < o){ ss[threadIdx.x]+=ss[threadIdx.x+o]; qq[threadIdx.x]+=qq[threadIdx.x+o]; }
        __syncthreads();
    }
    if (threadIdx.x==0){
        float mean = ss[0]/(float)NHW;
        float var  = qq[0]/(float)NHW - mean*mean;
        float sc = g[c]*rsqrtf(var + 1e-5f);
        g_scale1[c]=sc; g_shift1[c]=b[c]-mean*sc;
    }
}

// ---------------- x1 = conv(feat, w_out) ; inp = x1 + relu(bn(z)) --------------
// reg-staged pipeline, double-buffered 34x34 tile, 4 rows/thread
__global__ __launch_bounds__(256) void wout_inp_k(
    const float* __restrict__ feat, const float* __restrict__ wt)
{
    __shared__ float tile[2][34][34];
    __shared__ float wsm[32*9];
    const int tid = threadIdx.y*32 + threadIdx.x;
    const int tx = threadIdx.x, ty = threadIdx.y;
    const int n = blockIdx.z;
    const int x0 = blockIdx.x*32, y0 = blockIdx.y*32;
    const int TSZ = 34*34;   // 1156
    const int NLD = 5;

    for (int i = tid; i < 288; i += 256) wsm[i] = wt[i];

    int off[NLD]; unsigned vmask = 0u;
    #pragma unroll
    for (int j=0;j<NLD;j++){
        int i = tid + j*256;
        int yy = i/34, xx = i - yy*34;
        int gy = y0+yy-1, gx = x0+xx-1;
        bool v = (i < TSZ) && ((unsigned)gy < HH) && ((unsigned)gx < WW);
        off[j] = v ? (gy*WW + gx) : 0;
        if (v) vmask |= (1u<<j);
    }
    {
        const float* src = feat + (size_t)(n*32)*HWSZ;
        float rld[NLD];
        #pragma unroll
        for (int j=0;j<NLD;j++) rld[j] = ((vmask>>j)&1u) ? src[off[j]] : 0.f;
        float* tb = &tile[0][0][0];
        #pragma unroll
        for (int j=0;j<NLD;j++){ int i = tid + j*256; if (i < TSZ) tb[i] = rld[j]; }
    }
    __syncthreads();

    float acc[4] = {0.f,0.f,0.f,0.f};
    for (int c = 0; c < 32; c++){
        const int cur = c & 1;
        float rld[NLD];
        if (c+1 < 32){
            const float* src = feat + (size_t)(n*32 + c+1)*HWSZ;
            #pragma unroll
            for (int j=0;j<NLD;j++) rld[j] = ((vmask>>j)&1u) ? src[off[j]] : 0.f;
        }
        #pragma unroll
        for (int r=0;r<3;r++)
        #pragma unroll
        for (int s=0;s<3;s++){
            float w = wsm[c*9 + r*3 + s];
            #pragma unroll
            for (int k=0;k<4;k++)
                acc[k] = fmaf(w, tile[cur][ty + 8*k + r][tx + s], acc[k]);
        }
        if (c+1 < 32){
            float* tb = &tile[cur^1][0][0];
            #pragma unroll
            for (int j=0;j<NLD;j++){ int i = tid + j*256; if (i < TSZ) tb[i] = rld[j]; }
        }
        __syncthreads();
    }
    float s2 = g_scale2[0], h2 = g_shift2[0];
    #pragma unroll
    for (int k=0;k<4;k++) {
        int idx = (y0+ty+8*k)*WW + x0 + tx;
        float zz = g_z[(size_t)n*HWSZ + idx];
        g_inp[(size_t)n*HWSZ + idx] = acc[k] + fmaxf(zz*s2 + h2, 0.f);
    }
}

// ---------------- z = sum_c relu(bn(auxb1_c)) * b2w_c  (+fused z partial stats)
__global__ __launch_bounds__(256) void b2_k(const float* __restrict__ w2)
{
    __shared__ float s[32], h[32], ww[32];
    if (threadIdx.x < 32){ s[threadIdx.x]=g_scale1[threadIdx.x];
                           h[threadIdx.x]=g_shift1[threadIdx.x];
                           ww[threadIdx.x]=w2[threadIdx.x]; }
    __syncthreads();
    int i = blockIdx.x*256 + threadIdx.x;
    int n = i / HWSZ, r = i - n*HWSZ;
    float acc = 0.f;
    #pragma unroll
    for (int c=0;c<32;c++){
        float v = g_auxb1[((size_t)(n*32+c))*HWSZ + r];
        acc += fmaxf(v*s[c]+h[c], 0.f)*ww[c];
    }
    g_z[i] = acc;
    __shared__ float ss[256], qq[256];
    ss[threadIdx.x]=acc; qq[threadIdx.x]=acc*acc;
    __syncthreads();
    for (int o=128;o>0;o>>=1){
        if (threadIdx.x < o){ ss[threadIdx.x]+=ss[threadIdx.x+o]; qq[threadIdx.x]+=qq[threadIdx.x+o]; }
        __syncthreads();
    }
    if (threadIdx.x==0){
        g_part[blockIdx.x*2+0]=ss[0];
        g_part[blockIdx.x*2+1]=qq[0];
    }
}

// reduce the 2048 b2 partials -> scale2/shift2
__global__ __launch_bounds__(256) void stats2z_k(const float* __restrict__ g,
                                                 const float* __restrict__ b)
{
    float s=0.f, q=0.f;
    for (int j = threadIdx.x; j < NHW/256; j += 256){
        s += g_part[j*2+0];
        q += g_part[j*2+1];
    }
    __shared__ float ss[256], qq[256];
    ss[threadIdx.x]=s; qq[threadIdx.x]=q;
    __syncthreads();
    for (int o=128;o>0;o>>=1){
        if (threadIdx.x < o){ ss[threadIdx.x]+=ss[threadIdx.x+o]; qq[threadIdx.x]+=qq[threadIdx.x+o]; }
        __syncthreads();
    }
    if (threadIdx.x==0){
        float mean = ss[0]/(float)NHW;
        float var  = qq[0]/(float)NHW - mean*mean;
        float sc = g[0]*rsqrtf(var + 1e-5f);
        g_scale2[0]=sc; g_shift2[0]=b[0]-mean*sc;
    }
}

// ---------------- xm9 = aff3(inp) + conv(inp, d0) ------------------------------
__global__ __launch_bounds__(256) void xm9_k(const float* __restrict__ d0)
{
    __shared__ float tile[10][34];
    __shared__ float wsm[81];
    const int n = blockIdx.z;
    const int x0 = blockIdx.x*32, y0 = blockIdx.y*8;
    const int tid = threadIdx.y*32 + threadIdx.x;
    if (tid < 81) wsm[tid] = d0[tid];
    for (int i = tid; i < 340; i += 256){
        int yy=i/34, xx=i%34;
        int gy=y0+yy-1, gx=x0+xx-1;
        tile[yy][xx] = ((unsigned)gy<HH && (unsigned)gx<WW) ? g_inp[(size_t)n*HWSZ + gy*WW + gx] : 0.f;
    }
    __syncthreads();
    float nb[3][3];
    #pragma unroll
    for (int r=0;r<3;r++)
    #pragma unroll
    for (int s=0;s<3;s++) nb[r][s] = tile[threadIdx.y+r][threadIdx.x+s];
    float ctr = nb[1][1];
    int idx = (y0+threadIdx.y)*WW + x0 + threadIdx.x;
    #pragma unroll
    for (int t=0;t<9;t++){
        int ii=t/3, jj=t%3;
        float cv=0.f;
        #pragma unroll
        for (int r=0;r<3;r++)
        #pragma unroll
        for (int s=0;s<3;s++) cv = fmaf(nb[r][s], wsm[t*9+r*3+s], cv);
        g_xm9[((size_t)(n*9+t))*HWSZ + idx] = fmaf(nb[ii][jj], ctr, cv);
    }
}

// ---------------- xm25 = aff5(inp) + conv(xm9, d1) -----------------------------
// block (32,8); all 25 outputs; 4 px/thread; tile 128x8; reg-staged prefetch
__global__ __launch_bounds__(256) void xm25_k(const float* __restrict__ d1)
{
    __shared__ float ti[12][132];
    __shared__ float t9[2][10][132];
    __shared__ float wsm[25*81];
    const int n = blockIdx.z;
    const int x0 = blockIdx.x*128, y0 = blockIdx.y*8;
    const int tid = threadIdx.y*32 + threadIdx.x;
    const int tx = threadIdx.x, ty = threadIdx.y;
    const int TSZ = 10*132;   // 1320
    const int NLD = 6;

    for (int i=tid;i<25*81;i+=256) wsm[i] = d1[i];
    for (int i=tid;i<12*132;i+=256){
        int yy=i/132, xx=i-yy*132;
        int gy=y0+yy-2, gx=x0+xx-2;
        ti[yy][xx] = ((unsigned)gy<HH && (unsigned)gx<WW) ? g_inp[(size_t)n*HWSZ + (size_t)gy*WW + gx] : 0.f;
    }

    int off[NLD]; unsigned vmask = 0u;
    #pragma unroll
    for (int j=0;j<NLD;j++){
        int i = tid + j*256;
        int yy = i/132, xx = i - yy*132;
        int gy = y0+yy-1, gx = x0+xx-1;
        bool v = (i < TSZ) && ((unsigned)gy < HH) && ((unsigned)gx < WW);
        off[j] = v ? (gy*WW + gx) : 0;
        if (v) vmask |= (1u<<j);
    }
    {
        const float* src = g_xm9 + (size_t)(n*9)*HWSZ;
        float rld[NLD];
        #pragma unroll
        for (int j=0;j<NLD;j++) rld[j] = ((vmask>>j)&1u) ? src[off[j]] : 0.f;
        float* tb = &t9[0][0][0];
        #pragma unroll
        for (int j=0;j<NLD;j++){ int i = tid + j*256; if (i < TSZ) tb[i] = rld[j]; }
    }
    __syncthreads();

    float acc[25][4];
    #pragma unroll
    for (int t=0;t<25;t++)
        #pragma unroll
        for (int k=0;k<4;k++) acc[t][k]=0.f;

    for (int c=0;c<9;c++){
        const int cur = c & 1;
        float rld[NLD];
        if (c+1 < 9){
            const float* src = g_xm9 + (size_t)(n*9 + c+1)*HWSZ;
            #pragma unroll
            for (int j=0;j<NLD;j++) rld[j] = ((vmask>>j)&1u) ? src[off[j]] : 0.f;
        }
        #pragma unroll
        for (int r=0;r<3;r++)
        #pragma unroll
        for (int s=0;s<3;s++){
            float v[4];
            #pragma unroll
            for (int k=0;k<4;k++) v[k] = t9[cur][ty + r][tx + 32*k + s];
            #pragma unroll
            for (int t=0;t<25;t++){
                float wv = wsm[t*81 + c*9 + r*3 + s];
                #pragma unroll
                for (int k=0;k<4;k++) acc[t][k] = fmaf(wv, v[k], acc[t][k]);
            }
        }
        if (c+1 < 9){
            float* tb = &t9[cur^1][0][0];
            #pragma unroll
            for (int j=0;j<NLD;j++){ int i = tid + j*256; if (i < TSZ) tb[i] = rld[j]; }
        }
        __syncthreads();
    }

    #pragma unroll
    for (int t=0;t<25;t++){
        const int ii = t/5, jj = t%5;
        #pragma unroll
        for (int k=0;k<4;k++){
            int lx = tx + 32*k;
            float ctr = ti[ty+2][lx+2];
            float aff = ti[ty+ii][lx+jj] * ctr;
            g_xm25[((size_t)(n*25+t))*HWSZ + (size_t)(y0+ty)*WW + x0 + lx] = aff + acc[t][k];
        }
    }
}

// ---------------- conv4d + affinity reduce + seg output ------------------------
__global__ __launch_bounds__(256) void final_k(const float* __restrict__ d4,
                                               float* __restrict__ segout)
{
    __shared__ float t25[25][10][34];
    __shared__ float ti[12][36];
    __shared__ float wsm[81];
    const int n = blockIdx.z;
    const int x0 = blockIdx.x*32, y0 = blockIdx.y*8;
    const int tid = threadIdx.y*32 + threadIdx.x;
    if (tid < 81) wsm[tid] = d4[tid];
    for (int i = tid; i < 25*340; i += 256){
        int c = i/340, rr = i - c*340, yy = rr/34, xx = rr%34;
        int gy=y0+yy-1, gx=x0+xx-1;
        t25[c][yy][xx] = ((unsigned)gy<HH && (unsigned)gx<WW) ? g_xm25[((size_t)(n*25+c))*HWSZ + gy*WW + gx] : 0.f;
    }
    for (int i=tid;i<432;i+=256){
        int yy=i/36, xx=i%36;
        int gy=y0+yy-2, gx=x0+xx-2;
        ti[yy][xx] = ((unsigned)gy<HH && (unsigned)gx<WW) ? g_inp[(size_t)n*HWSZ + gy*WW + gx] : 0.f;
    }
    __syncthreads();

    float kacc[25];
    #pragma unroll
    for (int t=0;t<25;t++) kacc[t]=0.f;

    #pragma unroll
    for (int r=0;r<3;r++)
    #pragma unroll
    for (int s=0;s<3;s++){
        float wv[9];
        #pragma unroll
        for (int p=0;p<3;p++)
        #pragma unroll
        for (int q=0;q<3;q++) wv[p*3+q] = wsm[((p*3+q)*3+r)*3 + s];
        float L[25];
        #pragma unroll
        for (int u=0;u<5;u++)
        #pragma unroll
        for (int v=0;v<5;v++) L[u*5+v] = t25[u*5+v][threadIdx.y+r][threadIdx.x+s];
        #pragma unroll
        for (int d=0;d<5;d++)
        #pragma unroll
        for (int e=0;e<5;e++)
        #pragma unroll
        for (int p=0;p<3;p++){
            int u = d-1+p; if (u < 0 || u > 4) continue;
            #pragma unroll
            for (int q=0;q<3;q++){
                int v = e-1+q; if (v < 0 || v > 4) continue;
                kacc[d*5+e] = fmaf(L[u*5+v], wv[p*3+q], kacc[d*5+e]);
            }
        }
    }
    float sum = 0.f;
    #pragma unroll
    for (int ii=0;ii<5;ii++)
    #pragma unroll
    for (int jj=0;jj<5;jj++)
        sum = fmaf(ti[threadIdx.y+ii][threadIdx.x+jj], kacc[ii*5+jj], sum);

    float o = sum / 25.0f;
    int idx = (y0+threadIdx.y)*WW + x0 + threadIdx.x;
    segout[((size_t)(n*2+0))*HWSZ + idx] = 1.0f - o;
    segout[((size_t)(n*2+1))*HWSZ + idx] = o;
}

// ---------------- top-k threshold: radix select on float keys ------------------
__device__ __forceinline__ unsigned f2key(float f){
    unsigned u = __float_as_uint(f);
    return (u & 0x80000000u) ? ~u : (u | 0x80000000u);
}
__device__ __forceinline__ float key2f(unsigned k){
    unsigned u = (k & 0x80000000u) ? (k & 0x7fffffffu) : ~k;
    return __uint_as_float(u);
}

__global__ void thr_init_k(const float* __restrict__ ratio)
{
    int t = threadIdx.x;
    unsigned* hflat = &g_hist[0][0];
    for (int i=t;i<4*256;i+=256) hflat[i]=0u;
    if (t < 4){
        int n = t >> 1;
        float fp = floorf(ratio[n]*(float)HWSZ);
        int k = (int)floorf(fp*0.1f);
        int idx = k-1; if (idx < 0) idx = 0;
        g_remain[t] = idx;
        g_prefix[t] = 0u;
    }
}

__global__ __launch_bounds__(256) void hist_k(const float* __restrict__ seg, int shift)
{
    __shared__ unsigned hh[256];
    const int j = blockIdx.y;
    hh[threadIdx.x]=0u;
    __syncthreads();
    unsigned pfx = g_prefix[j];
    unsigned mask = (shift==24) ? 0u : (0xFFFFFFFFu << (shift+8));
    const float* p = seg + (size_t)j*HWSZ;
    for (int i = blockIdx.x*256 + threadIdx.x; i < HWSZ; i += 64*256){
        unsigned key = f2key(p[i]);
        if ((key & mask) == pfx) atomicAdd(&hh[(key>>shift)&255u], 1u);
    }
    __syncthreads();
    if (hh[threadIdx.x]) atomicAdd(&g_hist[j][threadIdx.x], hh[threadIdx.x]);
}

__global__ void select_k(int shift, int last)
{
    int j = threadIdx.x;
    if (j >= 4) return;
    int rem = g_remain[j];
    unsigned pfx = g_prefix[j];
    int done = 0;
    for (int b=255;b>=0;b--){
        unsigned c = g_hist[j][b];
        if (!done){
            if ((int)c > rem){ pfx |= ((unsigned)b)<<shift; done=1; }
            else rem -= (int)c;
        }
        g_hist[j][b]=0u;
    }
    g_prefix[j]=pfx; g_remain[j]=rem;
    if (last) g_thr[j] = key2f(pfx);
}

__global__ __launch_bounds__(256) void erase_k(const float* __restrict__ seg,
                                               const float* __restrict__ x)
{
    int i = blockIdx.x*256 + threadIdx.x;
    if (i >= NHW) return;
    int n = i / HWSZ, r = i - n*HWSZ;
    float t0 = g_thr[n*2+0], t1 = g_thr[n*2+1];
    bool m = (seg[((size_t)(n*2+0))*HWSZ + r] > t0) || (seg[((size_t)(n*2+1))*HWSZ + r] > t1);
    #pragma unroll
    for (int c=0;c<3;c++)
        g_img2[((size_t)(n*3+c))*HWSZ + r] = m ? 0.f : x[((size_t)(n*3+c))*HWSZ + r];
}

// ---------------- host orchestration -------------------------------------------
struct Ptrs { float *feat, *aux, *auxb1; };

static void run_pipeline(const float* img, float* seg_out,
                         const float* w1, const float* wa, const float* wout,
                         const float* b1w, const float* b1g, const float* b1b,
                         const float* b2w, const float* b2g, const float* b2b,
                         const float* d0w, const float* d1w, const float* d4w,
                         const Ptrs& P)
{
    dim3 blk(32,8);
    dim3 gconv(16,8,NB*4);   // 32x64 tiles
    conv3x3_k<3,true,false ><<<gconv, blk>>>(img,    w1,  P.feat,  4);
    conv3x3_k<3,true,false ><<<gconv, blk>>>(img,    wa,  P.aux,   4);
    conv3x3_k<32,false,true><<<gconv, blk>>>(P.aux, b1w, P.auxb1, 4);
    stats2_k<<<32,256>>>(b1g, b1b);
    b2_k<<<NHW/256, 256>>>(b2w);
    stats2z_k<<<1,256>>>(b2g, b2b);
    wout_inp_k<<<dim3(16,16,NB), blk>>>(P.feat, wout);
    xm9_k<<<dim3(16,64,NB), blk>>>(d0w);
    xm25_k<<<dim3(4,64,NB), blk>>>(d1w);
    final_k<<<dim3(16,64,NB), blk>>>(d4w, seg_out);
}

extern "C" void kernel_launch(void* const* d_in, const int* in_sizes, int n_in,
                              void* d_out, int out_size)
{
    const float* x     = (const float*)d_in[0];
    const float* ratio = (const float*)d_in[1];
    const float* w1    = (const float*)d_in[2];
    const float* wa    = (const float*)d_in[3];
    const float* wout  = (const float*)d_in[4];
    const float* b1w   = (const float*)d_in[5];
    const float* b1g   = (const float*)d_in[6];
    const float* b1b   = (const float*)d_in[7];
    const float* b2w   = (const float*)d_in[8];
    const float* b2g   = (const float*)d_in[9];
    const float* b2b   = (const float*)d_in[10];
    const float* d0w   = (const float*)d_in[11];
    const float* d1w   = (const float*)d_in[12];
    const float* d4w   = (const float*)d_in[13];
    float* out = (float*)d_out;

    Ptrs P;
    void* p;
    cudaGetSymbolAddress(&p, g_feat);   P.feat   = (float*)p;
    cudaGetSymbolAddress(&p, g_aux);    P.aux    = (float*)p;
    cudaGetSymbolAddress(&p, g_auxb1);  P.auxb1  = (float*)p;
    float* img2; cudaGetSymbolAddress(&p, g_img2); img2 = (float*)p;

    // pipeline 1 -> x1 (first half of output)
    run_pipeline(x, out, w1, wa, wout, b1w, b1g, b1b, b2w, b2g, b2b,
                 d0w, d1w, d4w, P);

    // erasing: per-(n,c) radix select of the idx-th largest seg value
    thr_init_k<<<1,256>>>(ratio);
    for (int pass=0; pass<4; ++pass){
        int shift = 24 - 8*pass;
        hist_k<<<dim3(64,4), 256>>>(out, shift);
        select_k<<<1,4>>>(shift, pass==3 ? 1 : 0);
    }
    erase_k<<<(NHW+255)/256, 256>>>(out, x);

    // pipeline 2 -> x2 (second half of output)
    run_pipeline(img2, out + (size_t)NB*2*HWSZ, w1, wa, wout,
                 b1w, b1g, b1b, b2w, b2g, b2b, d0w, d1w, d4w, P);
}

// round 6
// speedup vs baseline: 1.6034x; 1.0167x over previous
#include <cuda_runtime.h>
#include <math.h>

#define HH 512
#define WW 512
#define NB 2
#define HWSZ (HH*WW)          // 262144
#define NHW (NB*HWSZ)         // 524288

// ---------------- scratch (device globals; no allocation allowed) -------------
__device__ float g_feat [NB*32*HWSZ];
__device__ float g_aux  [NB*32*HWSZ];
__device__ float g_auxb1[NB*32*HWSZ];
__device__ float g_z    [NHW];
__device__ float g_inp  [NHW];
__device__ float g_xm25 [NB*25*HWSZ];
__device__ float g_part [32*256*2];
__device__ float g_scale1[32], g_shift1[32];
__device__ float g_scale2[1],  g_shift2[1];
__device__ unsigned g_hist[4][256];
__device__ unsigned g_prefix[4];
__device__ int      g_remain[4];
__device__ float    g_thr[4];

// ---------------- fused dual 3x3 conv (3->32 twice): 16 oc x 4 rows/thread ----
// block (32,8); tile 32x32 (+halo); ERASE: apply results_erasing mask on load.
template<bool ERASE>
__global__ __launch_bounds__(256) void dualconv3_k(
    const float* __restrict__ img, const float* __restrict__ seg,
    const float* __restrict__ w1, const float* __restrict__ wa,
    float* __restrict__ feat, float* __restrict__ aux)
{
    __shared__ float tile[2][34][34];
    __shared__ float wsm[16*27];
    const int tid = threadIdx.y*32 + threadIdx.x;
    const int tx = threadIdx.x, ty = threadIdx.y;
    const int grp = blockIdx.z & 3;
    const int n   = blockIdx.z >> 2;
    const int oc0 = grp*8;
    const int x0 = blockIdx.x*32, y0 = blockIdx.y*32;
    const int TSZ = 34*34;
    const int NLD = 5;

    for (int i = tid; i < 16*27; i += 256){
        int o = i/27, rr = i - o*27;
        wsm[i] = (o < 8) ? w1[(oc0+o)*27 + rr] : wa[(oc0+o-8)*27 + rr];
    }

    int off[NLD]; unsigned vmask = 0u, emask = 0u;
    #pragma unroll
    for (int j=0;j<NLD;j++){
        int i = tid + j*256;
        int yy = i/34, xx = i - yy*34;
        int gy = y0+yy-1, gx = x0+xx-1;
        bool v = (i < TSZ) && ((unsigned)gy < HH) && ((unsigned)gx < WW);
        off[j] = v ? (gy*WW + gx) : 0;
        if (v) vmask |= (1u<<j);
    }
    if (ERASE){
        float t0 = g_thr[n*2+0], t1 = g_thr[n*2+1];
        #pragma unroll
        for (int j=0;j<NLD;j++){
            if ((vmask>>j)&1u){
                float s0 = seg[((size_t)(n*2+0))*HWSZ + off[j]];
                float s1 = seg[((size_t)(n*2+1))*HWSZ + off[j]];
                if (s0 > t0 || s1 > t1) emask |= (1u<<j);
            }
        }
    }

    // load channel 0
    {
        const float* src = img + (size_t)(n*3)*HWSZ;
        float rld[NLD];
        #pragma unroll
        for (int j=0;j<NLD;j++)
            rld[j] = (((vmask>>j)&1u) && !((emask>>j)&1u)) ? src[off[j]] : 0.f;
        float* tb = &tile[0][0][0];
        #pragma unroll
        for (int j=0;j<NLD;j++){ int i = tid + j*256; if (i < TSZ) tb[i] = rld[j]; }
    }
    __syncthreads();

    float acc[16][4];
    #pragma unroll
    for (int o=0;o<16;o++)
        #pragma unroll
        for (int k=0;k<4;k++) acc[o][k]=0.f;

    for (int c = 0; c < 3; c++){
        const int cur = c & 1;
        float rld[NLD];
        if (c+1 < 3){
            const float* src = img + (size_t)(n*3 + c+1)*HWSZ;
            #pragma unroll
            for (int j=0;j<NLD;j++)
                rld[j] = (((vmask>>j)&1u) && !((emask>>j)&1u)) ? src[off[j]] : 0.f;
        }
        #pragma unroll
        for (int r=0;r<3;r++)
        #pragma unroll
        for (int s=0;s<3;s++){
            float wv[16];
            #pragma unroll
            for (int o=0;o<16;o++) wv[o] = wsm[o*27 + c*9 + r*3 + s];
            #pragma unroll
            for (int k=0;k<4;k++){
                float v = tile[cur][ty + 8*k + r][tx + s];
                #pragma unroll
                for (int o=0;o<16;o++) acc[o][k] = fmaf(wv[o], v, acc[o][k]);
            }
        }
        if (c+1 < 3){
            float* tb = &tile[cur^1][0][0];
            #pragma unroll
            for (int j=0;j<NLD;j++){ int i = tid + j*256; if (i < TSZ) tb[i] = rld[j]; }
        }
        __syncthreads();
    }

    #pragma unroll
    for (int o=0;o<16;o++)
    #pragma unroll
    for (int k=0;k<4;k++){
        float v = fmaxf(acc[o][k], 0.f);
        size_t idx = (size_t)(y0+ty+8*k)*WW + x0 + tx;
        if (o < 8) feat[((size_t)(n*32 + oc0 + o  ))*HWSZ + idx] = v;
        else       aux [((size_t)(n*32 + oc0 + o-8))*HWSZ + idx] = v;
    }
}

// ---------------- 32->32 3x3 conv: 8 oc x 8 rows/thread, fused BN partials -----
__global__ __launch_bounds__(256) void conv32_k(
    const float* __restrict__ in, const float* __restrict__ wt,
    float* __restrict__ out)
{
    __shared__ float tile[2][66][34];
    __shared__ float wsm[8*32*9];
    const int tid = threadIdx.y*32 + threadIdx.x;
    const int tx = threadIdx.x, ty = threadIdx.y;
    const int grp = blockIdx.z & 3;
    const int n   = blockIdx.z >> 2;
    const int oc0 = grp*8;
    const int x0 = blockIdx.x*32, y0 = blockIdx.y*64;
    const int TSZ = 66*34;
    const int NLD = 9;

    for (int i = tid; i < 8*32*9; i += 256) wsm[i] = wt[oc0*32*9 + i];

    int off[NLD]; unsigned vmask = 0u;
    #pragma unroll
    for (int j=0;j<NLD;j++){
        int i = tid + j*256;
        int yy = i/34, xx = i - yy*34;
        int gy = y0+yy-1, gx = x0+xx-1;
        bool v = (i < TSZ) && ((unsigned)gy < HH) && ((unsigned)gx < WW);
        off[j] = v ? (gy*WW + gx) : 0;
        if (v) vmask |= (1u<<j);
    }

    {
        const float* src = in + (size_t)(n*32)*HWSZ;
        float rld[NLD];
        #pragma unroll
        for (int j=0;j<NLD;j++) rld[j] = ((vmask>>j)&1u) ? src[off[j]] : 0.f;
        float* tb = &tile[0][0][0];
        #pragma unroll
        for (int j=0;j<NLD;j++){ int i = tid + j*256; if (i < TSZ) tb[i] = rld[j]; }
    }
    __syncthreads();

    float acc[8][8];
    #pragma unroll
    for (int o=0;o<8;o++)
        #pragma unroll
        for (int k=0;k<8;k++) acc[o][k]=0.f;

    for (int c = 0; c < 32; c++){
        const int cur = c & 1;
        float rld[NLD];
        if (c+1 < 32){
            const float* src = in + (size_t)(n*32 + c+1)*HWSZ;
            #pragma unroll
            for (int j=0;j<NLD;j++) rld[j] = ((vmask>>j)&1u) ? src[off[j]] : 0.f;
        }
        #pragma unroll
        for (int r=0;r<3;r++){
            float wv[8][3];
            #pragma unroll
            for (int o=0;o<8;o++)
            #pragma unroll
            for (int s=0;s<3;s++)
                wv[o][s] = wsm[(o*32+c)*9 + r*3 + s];
            #pragma unroll
            for (int k=0;k<8;k++){
                const int row = ty + 8*k + r;
                float v0 = tile[cur][row][tx];
                float v1 = tile[cur][row][tx+1];
                float v2 = tile[cur][row][tx+2];
                #pragma unroll
                for (int o=0;o<8;o++){
                    acc[o][k] = fmaf(wv[o][0], v0, acc[o][k]);
                    acc[o][k] = fmaf(wv[o][1], v1, acc[o][k]);
                    acc[o][k] = fmaf(wv[o][2], v2, acc[o][k]);
                }
            }
        }
        if (c+1 < 32){
            float* tb = &tile[cur^1][0][0];
            #pragma unroll
            for (int j=0;j<NLD;j++){ int i = tid + j*256; if (i < TSZ) tb[i] = rld[j]; }
        }
        __syncthreads();
    }

    #pragma unroll
    for (int o=0;o<8;o++)
    #pragma unroll
    for (int k=0;k<8;k++)
        out[((size_t)(n*32 + oc0 + o))*HWSZ + (size_t)(y0+ty+8*k)*WW + x0 + tx] = acc[o][k];

    // deterministic per-block BN partials
    float* red = &tile[0][0][0];
    float s[8], q[8];
    #pragma unroll
    for (int o=0;o<8;o++){
        float sv=0.f, qv=0.f;
        #pragma unroll
        for (int k=0;k<8;k++){ float v=acc[o][k]; sv+=v; qv=fmaf(v,v,qv); }
        #pragma unroll
        for (int d=16; d>0; d>>=1){
            sv += __shfl_down_sync(0xffffffffu, sv, d);
            qv += __shfl_down_sync(0xffffffffu, qv, d);
        }
        s[o]=sv; q[o]=qv;
    }
    if (tx == 0){
        #pragma unroll
        for (int o=0;o<8;o++){ red[o*8+ty]=s[o]; red[64+o*8+ty]=q[o]; }
    }
    __syncthreads();
    if (tid < 8){
        float S=0.f, Q=0.f;
        #pragma unroll
        for (int w=0;w<8;w++){ S+=red[tid*8+w]; Q+=red[64+tid*8+w]; }
        int p = (n*gridDim.y + blockIdx.y)*gridDim.x + blockIdx.x;  // < 256
        g_part[((oc0+tid)*256+p)*2+0] = S;
        g_part[((oc0+tid)*256+p)*2+1] = Q;
    }
}

// ---------------- reduce conv32 partials -> scale1/shift1 ----------------------
__global__ __launch_bounds__(256) void stats2_k(const float* __restrict__ g,
                                                const float* __restrict__ b)
{
    const int c = blockIdx.x;
    __shared__ float ss[256], qq[256];
    ss[threadIdx.x] = g_part[(c*256+threadIdx.x)*2+0];
    qq[threadIdx.x] = g_part[(c*256+threadIdx.x)*2+1];
    __syncthreads();
    for (int o=128;o>0;o>>=1){
        if (threadIdx.x < o){ ss[threadIdx.x]+=ss[threadIdx.x+o]; qq[threadIdx.x]+=qq[threadIdx.x+o]; }
        __syncthreads();
    }
    if (threadIdx.x==0){
        float mean = ss[0]/(float)NHW;
        float var  = qq[0]/(float)NHW - mean*mean;
        float sc = g[c]*rsqrtf(var + 1e-5f);
        g_scale1[c]=sc; g_shift1[c]=b[c]-mean*sc;
    }
}

// ---------------- z = sum_c relu(bn(auxb1_c)) * b2w_c  (+fused z partial stats)
__global__ __launch_bounds__(256) void b2_k(const float* __restrict__ w2)
{
    __shared__ float s[32], h[32], ww[32];
    if (threadIdx.x < 32){ s[threadIdx.x]=g_scale1[threadIdx.x];
                           h[threadIdx.x]=g_shift1[threadIdx.x];
                           ww[threadIdx.x]=w2[threadIdx.x]; }
    __syncthreads();
    int i = blockIdx.x*256 + threadIdx.x;
    int n = i / HWSZ, r = i - n*HWSZ;
    float acc = 0.f;
    #pragma unroll
    for (int c=0;c<32;c++){
        float v = g_auxb1[((size_t)(n*32+c))*HWSZ + r];
        acc += fmaxf(v*s[c]+h[c], 0.f)*ww[c];
    }
    g_z[i] = acc;
    __shared__ float ss[256], qq[256];
    ss[threadIdx.x]=acc; qq[threadIdx.x]=acc*acc;
    __syncthreads();
    for (int o=128;o>0;o>>=1){
        if (threadIdx.x < o){ ss[threadIdx.x]+=ss[threadIdx.x+o]; qq[threadIdx.x]+=qq[threadIdx.x+o]; }
        __syncthreads();
    }
    if (threadIdx.x==0){
        g_part[blockIdx.x*2+0]=ss[0];
        g_part[blockIdx.x*2+1]=qq[0];
    }
}

__global__ __launch_bounds__(256) void stats2z_k(const float* __restrict__ g,
                                                 const float* __restrict__ b)
{
    float s=0.f, q=0.f;
    for (int j = threadIdx.x; j < NHW/256; j += 256){
        s += g_part[j*2+0];
        q += g_part[j*2+1];
    }
    __shared__ float ss[256], qq[256];
    ss[threadIdx.x]=s; qq[threadIdx.x]=q;
    __syncthreads();
    for (int o=128;o>0;o>>=1){
        if (threadIdx.x < o){ ss[threadIdx.x]+=ss[threadIdx.x+o]; qq[threadIdx.x]+=qq[threadIdx.x+o]; }
        __syncthreads();
    }
    if (threadIdx.x==0){
        float mean = ss[0]/(float)NHW;
        float var  = qq[0]/(float)NHW - mean*mean;
        float sc = g[0]*rsqrtf(var + 1e-5f);
        g_scale2[0]=sc; g_shift2[0]=b[0]-mean*sc;
    }
}

// ---------------- x1 = conv(feat, w_out) ; inp = x1 + relu(bn(z)) --------------
// 8 rows/thread, tile 32x64, reg-staged double buffer
__global__ __launch_bounds__(256) void wout_inp_k(
    const float* __restrict__ feat, const float* __restrict__ wt)
{
    __shared__ float tile[2][66][34];
    __shared__ float wsm[32*9];
    const int tid = threadIdx.y*32 + threadIdx.x;
    const int tx = threadIdx.x, ty = threadIdx.y;
    const int n = blockIdx.z;
    const int x0 = blockIdx.x*32, y0 = blockIdx.y*64;
    const int TSZ = 66*34;
    const int NLD = 9;

    for (int i = tid; i < 288; i += 256) wsm[i] = wt[i];

    int off[NLD]; unsigned vmask = 0u;
    #pragma unroll
    for (int j=0;j<NLD;j++){
        int i = tid + j*256;
        int yy = i/34, xx = i - yy*34;
        int gy = y0+yy-1, gx = x0+xx-1;
        bool v = (i < TSZ) && ((unsigned)gy < HH) && ((unsigned)gx < WW);
        off[j] = v ? (gy*WW + gx) : 0;
        if (v) vmask |= (1u<<j);
    }
    {
        const float* src = feat + (size_t)(n*32)*HWSZ;
        float rld[NLD];
        #pragma unroll
        for (int j=0;j<NLD;j++) rld[j] = ((vmask>>j)&1u) ? src[off[j]] : 0.f;
        float* tb = &tile[0][0][0];
        #pragma unroll
        for (int j=0;j<NLD;j++){ int i = tid + j*256; if (i < TSZ) tb[i] = rld[j]; }
    }
    __syncthreads();

    float acc[8] = {0.f,0.f,0.f,0.f,0.f,0.f,0.f,0.f};
    for (int c = 0; c < 32; c++){
        const int cur = c & 1;
        float rld[NLD];
        if (c+1 < 32){
            const float* src = feat + (size_t)(n*32 + c+1)*HWSZ;
            #pragma unroll
            for (int j=0;j<NLD;j++) rld[j] = ((vmask>>j)&1u) ? src[off[j]] : 0.f;
        }
        #pragma unroll
        for (int r=0;r<3;r++)
        #pragma unroll
        for (int s=0;s<3;s++){
            float w = wsm[c*9 + r*3 + s];
            #pragma unroll
            for (int k=0;k<8;k++)
                acc[k] = fmaf(w, tile[cur][ty + 8*k + r][tx + s], acc[k]);
        }
        if (c+1 < 32){
            float* tb = &tile[cur^1][0][0];
            #pragma unroll
            for (int j=0;j<NLD;j++){ int i = tid + j*256; if (i < TSZ) tb[i] = rld[j]; }
        }
        __syncthreads();
    }
    float s2 = g_scale2[0], h2 = g_shift2[0];
    #pragma unroll
    for (int k=0;k<8;k++){
        int idx = (y0+ty+8*k)*WW + x0 + tx;
        float zz = g_z[(size_t)n*HWSZ + idx];
        g_inp[(size_t)n*HWSZ + idx] = acc[k] + fmaxf(zz*s2 + h2, 0.f);
    }
}

// ---------------- xm25 = aff5(inp) + conv(xm9(inp), d1), xm9 fused -------------
// block (32,8); 25 outputs; 4 px/thread; out tile 128x8
__global__ __launch_bounds__(256) void xm25f_k(const float* __restrict__ d0,
                                               const float* __restrict__ d1)
{
    __shared__ float ti[12][132];     // inp: rows y0-2..y0+9, cols x0-2..x0+129
    __shared__ float t9[10][132];     // xm9 ch c: rows y0-1..y0+8, cols x0-1..x0+128
    __shared__ float w0sm[81];
    __shared__ float w1sm[25*81];
    const int n = blockIdx.z;
    const int x0 = blockIdx.x*128, y0 = blockIdx.y*8;
    const int tid = threadIdx.y*32 + threadIdx.x;
    const int tx = threadIdx.x, ty = threadIdx.y;

    if (tid < 81) w0sm[tid] = d0[tid];
    for (int i=tid;i<25*81;i+=256) w1sm[i] = d1[i];
    for (int i=tid;i<12*132;i+=256){
        int yy=i/132, xx=i-yy*132;
        int gy=y0+yy-2, gx=x0+xx-2;
        ti[yy][xx] = ((unsigned)gy<HH && (unsigned)gx<WW) ? g_inp[(size_t)n*HWSZ + (size_t)gy*WW + gx] : 0.f;
    }
    __syncthreads();

    float acc[25][4];
    #pragma unroll
    for (int t=0;t<25;t++)
        #pragma unroll
        for (int k=0;k<4;k++) acc[t][k]=0.f;

    for (int c=0;c<9;c++){
        // compute xm9 channel c tile from inp tile (zero outside image)
        const int ii = c/3, jj = c%3;
        float w0[9];
        #pragma unroll
        for (int u=0;u<9;u++) w0[u] = w0sm[c*9+u];
        for (int i=tid;i<10*130;i+=256){
            int yy=i/130, xx=i-yy*130;
            int gy=y0+yy-1, gx=x0+xx-1;
            float val = 0.f;
            if ((unsigned)gy<HH && (unsigned)gx<WW){
                float ctr = ti[yy+1][xx+1];
                val = ti[yy+ii][xx+jj]*ctr;
                #pragma unroll
                for (int r=0;r<3;r++)
                #pragma unroll
                for (int s=0;s<3;s++)
                    val = fmaf(ti[yy+r][xx+s], w0[r*3+s], val);
            }
            t9[yy][xx] = val;
        }
        __syncthreads();

        #pragma unroll
        for (int r=0;r<3;r++)
        #pragma unroll
        for (int s=0;s<3;s++){
            float v[4];
            #pragma unroll
            for (int k=0;k<4;k++) v[k] = t9[ty + r][tx + 32*k + s];
            #pragma unroll
            for (int t=0;t<25;t++){
                float wv = w1sm[t*81 + c*9 + r*3 + s];
                #pragma unroll
                for (int k=0;k<4;k++) acc[t][k] = fmaf(wv, v[k], acc[t][k]);
            }
        }
        __syncthreads();
    }

    #pragma unroll
    for (int t=0;t<25;t++){
        const int ai = t/5, aj = t%5;
        #pragma unroll
        for (int k=0;k<4;k++){
            int lx = tx + 32*k;
            float ctr = ti[ty+2][lx+2];
            float aff = ti[ty+ai][lx+aj] * ctr;
            g_xm25[((size_t)(n*25+t))*HWSZ + (size_t)(y0+ty)*WW + x0 + lx] = aff + acc[t][k];
        }
    }
}

// ---------------- conv4d + affinity reduce + seg output ------------------------
__global__ __launch_bounds__(256) void final_k(const float* __restrict__ d4,
                                               float* __restrict__ segout)
{
    __shared__ float t25[25][10][34];
    __shared__ float ti[12][36];
    __shared__ float wsm[81];
    const int n = blockIdx.z;
    const int x0 = blockIdx.x*32, y0 = blockIdx.y*8;
    const int tid = threadIdx.y*32 + threadIdx.x;
    if (tid < 81) wsm[tid] = d4[tid];
    for (int i = tid; i < 25*340; i += 256){
        int c = i/340, rr = i - c*340, yy = rr/34, xx = rr%34;
        int gy=y0+yy-1, gx=x0+xx-1;
        t25[c][yy][xx] = ((unsigned)gy<HH && (unsigned)gx<WW) ? g_xm25[((size_t)(n*25+c))*HWSZ + gy*WW + gx] : 0.f;
    }
    for (int i=tid;i<432;i+=256){
        int yy=i/36, xx=i%36;
        int gy=y0+yy-2, gx=x0+xx-2;
        ti[yy][xx] = ((unsigned)gy<HH && (unsigned)gx<WW) ? g_inp[(size_t)n*HWSZ + gy*WW + gx] : 0.f;
    }
    __syncthreads();

    float kacc[25];
    #pragma unroll
    for (int t=0;t<25;t++) kacc[t]=0.f;

    #pragma unroll
    for (int r=0;r<3;r++)
    #pragma unroll
    for (int s=0;s<3;s++){
        float wv[9];
        #pragma unroll
        for (int p=0;p<3;p++)
        #pragma unroll
        for (int q=0;q<3;q++) wv[p*3+q] = wsm[((p*3+q)*3+r)*3 + s];
        float L[25];
        #pragma unroll
        for (int u=0;u<5;u++)
        #pragma unroll
        for (int v=0;v<5;v++) L[u*5+v] = t25[u*5+v][threadIdx.y+r][threadIdx.x+s];
        #pragma unroll
        for (int d=0;d<5;d++)
        #pragma unroll
        for (int e=0;e<5;e++)
        #pragma unroll
        for (int p=0;p<3;p++){
            int u = d-1+p; if (u < 0 || u > 4) continue;
            #pragma unroll
            for (int q=0;q<3;q++){
                int v = e-1+q; if (v < 0 || v > 4) continue;
                kacc[d*5+e] = fmaf(L[u*5+v], wv[p*3+q], kacc[d*5+e]);
            }
        }
    }
    float sum = 0.f;
    #pragma unroll
    for (int ii=0;ii<5;ii++)
    #pragma unroll
    for (int jj=0;jj<5;jj++)
        sum = fmaf(ti[threadIdx.y+ii][threadIdx.x+jj], kacc[ii*5+jj], sum);

    float o = sum / 25.0f;
    int idx = (y0+threadIdx.y)*WW + x0 + threadIdx.x;
    segout[((size_t)(n*2+0))*HWSZ + idx] = 1.0f - o;
    segout[((size_t)(n*2+1))*HWSZ + idx] = o;
}

// ---------------- top-k threshold: radix select on float keys ------------------
__device__ __forceinline__ unsigned f2key(float f){
    unsigned u = __float_as_uint(f);
    return (u & 0x80000000u) ? ~u : (u | 0x80000000u);
}
__device__ __forceinline__ float key2f(unsigned k){
    unsigned u = (k & 0x80000000u) ? (k & 0x7fffffffu) : ~k;
    return __uint_as_float(u);
}

__global__ __launch_bounds__(256) void hist_k(const float* __restrict__ seg, int shift)
{
    __shared__ unsigned hh[256];
    const int j = blockIdx.y;
    hh[threadIdx.x]=0u;
    __syncthreads();
    const bool first = (shift == 24);
    unsigned pfx = first ? 0u : g_prefix[j];
    unsigned mask = first ? 0u : (0xFFFFFFFFu << (shift+8));
    const float* p = seg + (size_t)j*HWSZ;
    for (int i = blockIdx.x*256 + threadIdx.x; i < HWSZ; i += 64*256){
        unsigned key = f2key(p[i]);
        if (first || (key & mask) == pfx) atomicAdd(&hh[(key>>shift)&255u], 1u);
    }
    __syncthreads();
    if (hh[threadIdx.x]) atomicAdd(&g_hist[j][threadIdx.x], hh[threadIdx.x]);
}

__global__ void select_k(const float* __restrict__ ratio, int shift,
                         int first, int last)
{
    int j = threadIdx.x;
    if (j >= 4) return;
    int rem; unsigned pfx;
    if (first){
        int n = j >> 1;
        float fp = floorf(ratio[n]*(float)HWSZ);
        int k = (int)floorf(fp*0.1f);
        rem = k-1; if (rem < 0) rem = 0;
        pfx = 0u;
    } else {
        rem = g_remain[j]; pfx = g_prefix[j];
    }
    int done = 0;
    for (int b=255;b>=0;b--){
        unsigned c = g_hist[j][b];
        if (!done){
            if ((int)c > rem){ pfx |= ((unsigned)b)<<shift; done=1; }
            else rem -= (int)c;
        }
        g_hist[j][b]=0u;
    }
    g_prefix[j]=pfx; g_remain[j]=rem;
    if (last) g_thr[j] = key2f(pfx);
}

// ---------------- host orchestration -------------------------------------------
struct Ptrs { float *feat, *aux, *auxb1; };

template<bool ERASE>
static void run_pipeline(const float* img, const float* seg, float* seg_out,
                         const float* w1, const float* wa, const float* wout,
                         const float* b1w, const float* b1g, const float* b1b,
                         const float* b2w, const float* b2g, const float* b2b,
                         const float* d0w, const float* d1w, const float* d4w,
                         const Ptrs& P)
{
    dim3 blk(32,8);
    dualconv3_k<ERASE><<<dim3(16,16,NB*4), blk>>>(img, seg, w1, wa, P.feat, P.aux);
    conv32_k<<<dim3(16,8,NB*4), blk>>>(P.aux, b1w, P.auxb1);
    stats2_k<<<32,256>>>(b1g, b1b);
    b2_k<<<NHW/256, 256>>>(b2w);
    stats2z_k<<<1,256>>>(b2g, b2b);
    wout_inp_k<<<dim3(16,8,NB), blk>>>(P.feat, wout);
    xm25f_k<<<dim3(4,64,NB), blk>>>(d0w, d1w);
    final_k<<<dim3(16,64,NB), blk>>>(d4w, seg_out);
}

extern "C" void kernel_launch(void* const* d_in, const int* in_sizes, int n_in,
                              void* d_out, int out_size)
{
    const float* x     = (const float*)d_in[0];
    const float* ratio = (const float*)d_in[1];
    const float* w1    = (const float*)d_in[2];
    const float* wa    = (const float*)d_in[3];
    const float* wout  = (const float*)d_in[4];
    const float* b1w   = (const float*)d_in[5];
    const float* b1g   = (const float*)d_in[6];
    const float* b1b   = (const float*)d_in[7];
    const float* b2w   = (const float*)d_in[8];
    const float* b2g   = (const float*)d_in[9];
    const float* b2b   = (const float*)d_in[10];
    const float* d0w   = (const float*)d_in[11];
    const float* d1w   = (const float*)d_in[12];
    const float* d4w   = (const float*)d_in[13];
    float* out = (float*)d_out;

    Ptrs P;
    void* p;
    cudaGetSymbolAddress(&p, g_feat);   P.feat   = (float*)p;
    cudaGetSymbolAddress(&p, g_aux);    P.aux    = (float*)p;
    cudaGetSymbolAddress(&p, g_auxb1);  P.auxb1  = (float*)p;

    // pipeline 1 -> x1 (first half of output)
    run_pipeline<false>(x, nullptr, out, w1, wa, wout, b1w, b1g, b1b,
                        b2w, b2g, b2b, d0w, d1w, d4w, P);

    // erasing threshold: per-(n,c) radix select of the idx-th largest seg value
    for (int pass=0; pass<4; ++pass){
        int shift = 24 - 8*pass;
        hist_k<<<dim3(64,4), 256>>>(out, shift);
        select_k<<<1,4>>>(ratio, shift, pass==0 ? 1 : 0, pass==3 ? 1 : 0);
    }

    // pipeline 2 (erase fused into its dual conv3) -> x2 (second half)
    run_pipeline<true>(x, out, out + (size_t)NB*2*HWSZ, w1, wa, wout,
                       b1w, b1g, b1b, b2w, b2g, b2b, d0w, d1w, d4w, P);
}